// round 7
// baseline (speedup 1.0000x reference)
#include <cuda_runtime.h>

// Problem constants (fixed by the dataset)
#define T_TOK 16384
#define H_DIM 1024
#define E_NUM 16
#define F_DIM 2048
#define K_TOP 2
#define TK    (T_TOK * K_TOP)   // 32768 slots
#define N1    (2 * F_DIM)       // 4096 (gate/up interleaved)

#define BM 128
#define BN 128
#define BKs 8
#define MAX_TILES (TK / BM + E_NUM)   // 272 upper bound on sum ceil(cnt_e/128)

// -------- device scratch (allocation-free contract) --------
__device__ int   g_counts[E_NUM];
__device__ int   g_slots[E_NUM * TK];          // per-expert slot lists (2 MB)
__device__ int   g_numTiles;
__device__ int   g_tileE[MAX_TILES + 8];
__device__ int   g_tileRow[MAX_TILES + 8];
__device__ float g_inter[(size_t)TK * F_DIM];  // intermediate activations (256 MB)

// -------- 1) zero output + counters (must run every graph replay) --------
__global__ void k_init(float* __restrict__ out) {
    int i = blockIdx.x * blockDim.x + threadIdx.x;
    if (i < T_TOK * H_DIM) out[i] = 0.0f;
    if (i < E_NUM) g_counts[i] = 0;
}

// -------- 2) bucket slots per expert --------
__global__ void k_build(const int* __restrict__ topk_ids) {
    int i = blockIdx.x * blockDim.x + threadIdx.x;
    if (i < TK) {
        int e = topk_ids[i];
        int pos = atomicAdd(&g_counts[e], 1);
        g_slots[e * TK + pos] = i;   // slot = t*K + k
    }
}

// -------- 3) build compact (expert, rowTile) work list --------
__global__ void k_tilemap() {
    if (threadIdx.x == 0 && blockIdx.x == 0) {
        int idx = 0;
        for (int e = 0; e < E_NUM; e++) {
            int c = g_counts[e];
            for (int r = 0; r < c; r += BM) {
                g_tileE[idx] = e;
                g_tileRow[idx] = r;
                idx++;
            }
        }
        g_numTiles = idx;
    }
}

// -------- 4) grouped GEMM1: x @ W1[e] + b1, fused swiglu -> g_inter --------
__global__ __launch_bounds__(256) void k_gemm1(
    const float* __restrict__ hidden,   // [T, H]
    const float* __restrict__ W,        // [E, H, 2F]
    const float* __restrict__ bias)     // [E, 2F]
{
    int tileIdx = blockIdx.y;
    if (tileIdx >= g_numTiles) return;
    int e = g_tileE[tileIdx];
    int rowStart = g_tileRow[tileIdx];
    int rowsHere = min(BM, g_counts[e] - rowStart);
    int n0 = blockIdx.x * BN;

    __shared__ float As[BKs][BM];
    __shared__ float Bs[BKs][BN];
    __shared__ int   sTok[BM];
    __shared__ int   sSlot[BM];

    int tid = threadIdx.x;
    const int* slots = g_slots + e * TK + rowStart;
    if (tid < BM) {
        int slot = (tid < rowsHere) ? slots[tid] : 0;
        sSlot[tid] = slot;
        sTok[tid]  = slot / K_TOP;
    }
    __syncthreads();

    int aRow = tid >> 1;            // 0..127
    int aCol = (tid & 1) * 4;       // 0 or 4
    int bRow = tid >> 5;            // 0..7
    int bCol = (tid & 31) * 4;      // 0..124

    bool aValid = (aRow < rowsHere);
    const float* Aptr  = hidden + (size_t)sTok[aRow] * H_DIM + aCol;
    const float* Bbase = W + (size_t)e * H_DIM * N1 + n0 + bCol;

    int ty = tid >> 4, tx = tid & 15;
    float acc[8][8];
    #pragma unroll
    for (int i = 0; i < 8; i++)
        #pragma unroll
        for (int j = 0; j < 8; j++) acc[i][j] = 0.0f;

    for (int k0 = 0; k0 < H_DIM; k0 += BKs) {
        float4 av = aValid ? *(const float4*)(Aptr + k0) : make_float4(0.f, 0.f, 0.f, 0.f);
        float4 bv = *(const float4*)(Bbase + (size_t)(k0 + bRow) * N1);
        As[aCol + 0][aRow] = av.x; As[aCol + 1][aRow] = av.y;
        As[aCol + 2][aRow] = av.z; As[aCol + 3][aRow] = av.w;
        *(float4*)&Bs[bRow][bCol] = bv;
        __syncthreads();
        #pragma unroll
        for (int kk = 0; kk < BKs; kk++) {
            float a[8], b[8];
            #pragma unroll
            for (int i = 0; i < 8; i++) a[i] = As[kk][ty * 8 + i];
            #pragma unroll
            for (int j = 0; j < 8; j++) b[j] = Bs[kk][tx * 8 + j];
            #pragma unroll
            for (int i = 0; i < 8; i++)
                #pragma unroll
                for (int j = 0; j < 8; j++) acc[i][j] += a[i] * b[j];
        }
        __syncthreads();
    }

    // epilogue: bias + swiglu (pairs of interleaved cols), store to g_inter
    const float* bptr = bias + (size_t)e * N1 + n0 + tx * 8;
    #pragma unroll
    for (int i = 0; i < 8; i++) {
        int r = ty * 8 + i;
        if (r < rowsHere) {
            int slot = sSlot[r];
            float vals[4];
            #pragma unroll
            for (int p = 0; p < 4; p++) {
                float g = acc[i][2 * p]     + bptr[2 * p];
                float u = acc[i][2 * p + 1] + bptr[2 * p + 1];
                g = fminf(g, 7.0f);
                u = fminf(fmaxf(u, -7.0f), 7.0f);
                float glu = g / (1.0f + __expf(-1.702f * g));
                vals[p] = (u + 1.0f) * glu;
            }
            float* op = g_inter + (size_t)slot * F_DIM + (n0 >> 1) + tx * 4;
            *(float4*)op = make_float4(vals[0], vals[1], vals[2], vals[3]);
        }
    }
}

// -------- 5) grouped GEMM2: inter @ W2[e] + b2, weight + atomic combine --------
__global__ __launch_bounds__(256) void k_gemm2(
    const float* __restrict__ W,        // [E, F, H]
    const float* __restrict__ bias,     // [E, H]
    const float* __restrict__ tw,       // [T, K] flat -> index by slot
    float* __restrict__ out)            // [T, H]
{
    int tileIdx = blockIdx.y;
    if (tileIdx >= g_numTiles) return;
    int e = g_tileE[tileIdx];
    int rowStart = g_tileRow[tileIdx];
    int rowsHere = min(BM, g_counts[e] - rowStart);
    int n0 = blockIdx.x * BN;

    __shared__ float As[BKs][BM];
    __shared__ float Bs[BKs][BN];
    __shared__ int   sSlot[BM];
    __shared__ float sW[BM];

    int tid = threadIdx.x;
    const int* slots = g_slots + e * TK + rowStart;
    if (tid < BM) {
        int slot = (tid < rowsHere) ? slots[tid] : 0;
        sSlot[tid] = slot;
        sW[tid]    = tw[slot];
    }
    __syncthreads();

    int aRow = tid >> 1;
    int aCol = (tid & 1) * 4;
    int bRow = tid >> 5;
    int bCol = (tid & 31) * 4;

    bool aValid = (aRow < rowsHere);
    const float* Aptr  = g_inter + (size_t)sSlot[aRow] * F_DIM + aCol;
    const float* Bbase = W + (size_t)e * F_DIM * H_DIM + n0 + bCol;

    int ty = tid >> 4, tx = tid & 15;
    float acc[8][8];
    #pragma unroll
    for (int i = 0; i < 8; i++)
        #pragma unroll
        for (int j = 0; j < 8; j++) acc[i][j] = 0.0f;

    for (int k0 = 0; k0 < F_DIM; k0 += BKs) {
        float4 av = aValid ? *(const float4*)(Aptr + k0) : make_float4(0.f, 0.f, 0.f, 0.f);
        float4 bv = *(const float4*)(Bbase + (size_t)(k0 + bRow) * H_DIM);
        As[aCol + 0][aRow] = av.x; As[aCol + 1][aRow] = av.y;
        As[aCol + 2][aRow] = av.z; As[aCol + 3][aRow] = av.w;
        *(float4*)&Bs[bRow][bCol] = bv;
        __syncthreads();
        #pragma unroll
        for (int kk = 0; kk < BKs; kk++) {
            float a[8], b[8];
            #pragma unroll
            for (int i = 0; i < 8; i++) a[i] = As[kk][ty * 8 + i];
            #pragma unroll
            for (int j = 0; j < 8; j++) b[j] = Bs[kk][tx * 8 + j];
            #pragma unroll
            for (int i = 0; i < 8; i++)
                #pragma unroll
                for (int j = 0; j < 8; j++) acc[i][j] += a[i] * b[j];
        }
        __syncthreads();
    }

    // epilogue: bias, scale by routing weight, atomic combine into out[token]
    const float* bptr = bias + (size_t)e * H_DIM + n0 + tx * 8;
    #pragma unroll
    for (int i = 0; i < 8; i++) {
        int r = ty * 8 + i;
        if (r < rowsHere) {
            int slot = sSlot[r];
            float w = sW[r];
            int tok = slot / K_TOP;
            float* op = out + (size_t)tok * H_DIM + n0 + tx * 8;
            #pragma unroll
            for (int j = 0; j < 8; j++) {
                atomicAdd(op + j, w * (acc[i][j] + bptr[j]));
            }
        }
    }
}

extern "C" void kernel_launch(void* const* d_in, const int* in_sizes, int n_in,
                              void* d_out, int out_size) {
    const float* hidden = (const float*)d_in[0];   // [T, H]
    const float* tw     = (const float*)d_in[1];   // [T, K]
    const int*   ids    = (const int*)d_in[2];     // [T, K]
    const float* w1     = (const float*)d_in[3];   // [E, H, 2F]
    const float* b1     = (const float*)d_in[4];   // [E, 2F]
    const float* w2     = (const float*)d_in[5];   // [E, F, H]
    const float* b2     = (const float*)d_in[6];   // [E, H]
    float* out = (float*)d_out;                    // [T, H]

    int n = T_TOK * H_DIM;
    k_init<<<(n + 255) / 256, 256>>>(out);
    k_build<<<(TK + 255) / 256, 256>>>(ids);
    k_tilemap<<<1, 32>>>();
    k_gemm1<<<dim3(N1 / BN, MAX_TILES), 256>>>(hidden, w1, b1);
    k_gemm2<<<dim3(H_DIM / BN, MAX_TILES), 256>>>(w2, b2, tw, out);
}

// round 8
// speedup vs baseline: 1.0012x; 1.0012x over previous
#include <cuda_runtime.h>

// Problem constants (fixed by the dataset)
#define T_TOK 16384
#define H_DIM 1024
#define E_NUM 16
#define F_DIM 2048
#define K_TOP 2
#define TK    (T_TOK * K_TOP)   // 32768 slots
#define N1    (2 * F_DIM)       // 4096 (gate/up interleaved)

#define BM 128
#define BN 128
#define BKs 8
#define MAX_TILES (TK / BM + E_NUM)   // 272 upper bound on sum ceil(cnt_e/128)

// -------- device scratch (allocation-free contract) --------
__device__ int   g_counts[E_NUM];
__device__ int   g_slots[E_NUM * TK];          // per-expert slot lists (2 MB)
__device__ int   g_numTiles;
__device__ int   g_tileE[MAX_TILES + 8];
__device__ int   g_tileRow[MAX_TILES + 8];
__device__ float g_inter[(size_t)TK * F_DIM];  // intermediate activations (256 MB)

// -------- 1) zero output + counters (must run every graph replay) --------
__global__ void k_init(float* __restrict__ out) {
    int i = blockIdx.x * blockDim.x + threadIdx.x;
    if (i < T_TOK * H_DIM) out[i] = 0.0f;
    if (i < E_NUM) g_counts[i] = 0;
}

// -------- 2) bucket slots per expert --------
__global__ void k_build(const int* __restrict__ topk_ids) {
    int i = blockIdx.x * blockDim.x + threadIdx.x;
    if (i < TK) {
        int e = topk_ids[i];
        int pos = atomicAdd(&g_counts[e], 1);
        g_slots[e * TK + pos] = i;   // slot = t*K + k
    }
}

// -------- 3) build compact (expert, rowTile) work list --------
__global__ void k_tilemap() {
    if (threadIdx.x == 0 && blockIdx.x == 0) {
        int idx = 0;
        for (int e = 0; e < E_NUM; e++) {
            int c = g_counts[e];
            for (int r = 0; r < c; r += BM) {
                g_tileE[idx] = e;
                g_tileRow[idx] = r;
                idx++;
            }
        }
        g_numTiles = idx;
    }
}

// -------- 4) grouped GEMM1: x @ W1[e] + b1, fused swiglu -> g_inter --------
__global__ __launch_bounds__(256) void k_gemm1(
    const float* __restrict__ hidden,   // [T, H]
    const float* __restrict__ W,        // [E, H, 2F]
    const float* __restrict__ bias)     // [E, 2F]
{
    int tileIdx = blockIdx.y;
    if (tileIdx >= g_numTiles) return;
    int e = g_tileE[tileIdx];
    int rowStart = g_tileRow[tileIdx];
    int rowsHere = min(BM, g_counts[e] - rowStart);
    int n0 = blockIdx.x * BN;

    __shared__ float As[BKs][BM];
    __shared__ float Bs[BKs][BN];
    __shared__ int   sTok[BM];
    __shared__ int   sSlot[BM];

    int tid = threadIdx.x;
    const int* slots = g_slots + e * TK + rowStart;
    if (tid < BM) {
        int slot = (tid < rowsHere) ? slots[tid] : 0;
        sSlot[tid] = slot;
        sTok[tid]  = slot / K_TOP;
    }
    __syncthreads();

    int aRow = tid >> 1;            // 0..127
    int aCol = (tid & 1) * 4;       // 0 or 4
    int bRow = tid >> 5;            // 0..7
    int bCol = (tid & 31) * 4;      // 0..124

    bool aValid = (aRow < rowsHere);
    const float* Aptr  = hidden + (size_t)sTok[aRow] * H_DIM + aCol;
    const float* Bbase = W + (size_t)e * H_DIM * N1 + n0 + bCol;

    int ty = tid >> 4, tx = tid & 15;
    float acc[8][8];
    #pragma unroll
    for (int i = 0; i < 8; i++)
        #pragma unroll
        for (int j = 0; j < 8; j++) acc[i][j] = 0.0f;

    for (int k0 = 0; k0 < H_DIM; k0 += BKs) {
        float4 av = aValid ? *(const float4*)(Aptr + k0) : make_float4(0.f, 0.f, 0.f, 0.f);
        float4 bv = *(const float4*)(Bbase + (size_t)(k0 + bRow) * N1);
        As[aCol + 0][aRow] = av.x; As[aCol + 1][aRow] = av.y;
        As[aCol + 2][aRow] = av.z; As[aCol + 3][aRow] = av.w;
        *(float4*)&Bs[bRow][bCol] = bv;
        __syncthreads();
        #pragma unroll
        for (int kk = 0; kk < BKs; kk++) {
            float a[8], b[8];
            #pragma unroll
            for (int i = 0; i < 8; i++) a[i] = As[kk][ty * 8 + i];
            #pragma unroll
            for (int j = 0; j < 8; j++) b[j] = Bs[kk][tx * 8 + j];
            #pragma unroll
            for (int i = 0; i < 8; i++)
                #pragma unroll
                for (int j = 0; j < 8; j++) acc[i][j] += a[i] * b[j];
        }
        __syncthreads();
    }

    // epilogue: bias + swiglu (pairs of interleaved cols), store to g_inter
    const float* bptr = bias + (size_t)e * N1 + n0 + tx * 8;
    #pragma unroll
    for (int i = 0; i < 8; i++) {
        int r = ty * 8 + i;
        if (r < rowsHere) {
            int slot = sSlot[r];
            float vals[4];
            #pragma unroll
            for (int p = 0; p < 4; p++) {
                float g = acc[i][2 * p]     + bptr[2 * p];
                float u = acc[i][2 * p + 1] + bptr[2 * p + 1];
                g = fminf(g, 7.0f);
                u = fminf(fmaxf(u, -7.0f), 7.0f);
                float glu = g / (1.0f + __expf(-1.702f * g));
                vals[p] = (u + 1.0f) * glu;
            }
            float* op = g_inter + (size_t)slot * F_DIM + (n0 >> 1) + tx * 4;
            *(float4*)op = make_float4(vals[0], vals[1], vals[2], vals[3]);
        }
    }
}

// -------- 5) grouped GEMM2: inter @ W2[e] + b2, weight + atomic combine --------
__global__ __launch_bounds__(256) void k_gemm2(
    const float* __restrict__ W,        // [E, F, H]
    const float* __restrict__ bias,     // [E, H]
    const float* __restrict__ tw,       // [T, K] flat -> index by slot
    float* __restrict__ out)            // [T, H]
{
    int tileIdx = blockIdx.y;
    if (tileIdx >= g_numTiles) return;
    int e = g_tileE[tileIdx];
    int rowStart = g_tileRow[tileIdx];
    int rowsHere = min(BM, g_counts[e] - rowStart);
    int n0 = blockIdx.x * BN;

    __shared__ float As[BKs][BM];
    __shared__ float Bs[BKs][BN];
    __shared__ int   sSlot[BM];
    __shared__ float sW[BM];

    int tid = threadIdx.x;
    const int* slots = g_slots + e * TK + rowStart;
    if (tid < BM) {
        int slot = (tid < rowsHere) ? slots[tid] : 0;
        sSlot[tid] = slot;
        sW[tid]    = tw[slot];
    }
    __syncthreads();

    int aRow = tid >> 1;
    int aCol = (tid & 1) * 4;
    int bRow = tid >> 5;
    int bCol = (tid & 31) * 4;

    bool aValid = (aRow < rowsHere);
    const float* Aptr  = g_inter + (size_t)sSlot[aRow] * F_DIM + aCol;
    const float* Bbase = W + (size_t)e * F_DIM * H_DIM + n0 + bCol;

    int ty = tid >> 4, tx = tid & 15;
    float acc[8][8];
    #pragma unroll
    for (int i = 0; i < 8; i++)
        #pragma unroll
        for (int j = 0; j < 8; j++) acc[i][j] = 0.0f;

    for (int k0 = 0; k0 < F_DIM; k0 += BKs) {
        float4 av = aValid ? *(const float4*)(Aptr + k0) : make_float4(0.f, 0.f, 0.f, 0.f);
        float4 bv = *(const float4*)(Bbase + (size_t)(k0 + bRow) * H_DIM);
        As[aCol + 0][aRow] = av.x; As[aCol + 1][aRow] = av.y;
        As[aCol + 2][aRow] = av.z; As[aCol + 3][aRow] = av.w;
        *(float4*)&Bs[bRow][bCol] = bv;
        __syncthreads();
        #pragma unroll
        for (int kk = 0; kk < BKs; kk++) {
            float a[8], b[8];
            #pragma unroll
            for (int i = 0; i < 8; i++) a[i] = As[kk][ty * 8 + i];
            #pragma unroll
            for (int j = 0; j < 8; j++) b[j] = Bs[kk][tx * 8 + j];
            #pragma unroll
            for (int i = 0; i < 8; i++)
                #pragma unroll
                for (int j = 0; j < 8; j++) acc[i][j] += a[i] * b[j];
        }
        __syncthreads();
    }

    // epilogue: bias, scale by routing weight, atomic combine into out[token]
    const float* bptr = bias + (size_t)e * H_DIM + n0 + tx * 8;
    #pragma unroll
    for (int i = 0; i < 8; i++) {
        int r = ty * 8 + i;
        if (r < rowsHere) {
            int slot = sSlot[r];
            float w = sW[r];
            int tok = slot / K_TOP;
            float* op = out + (size_t)tok * H_DIM + n0 + tx * 8;
            #pragma unroll
            for (int j = 0; j < 8; j++) {
                atomicAdd(op + j, w * (acc[i][j] + bptr[j]));
            }
        }
    }
}

extern "C" void kernel_launch(void* const* d_in, const int* in_sizes, int n_in,
                              void* d_out, int out_size) {
    const float* hidden = (const float*)d_in[0];   // [T, H]
    const float* tw     = (const float*)d_in[1];   // [T, K]
    const int*   ids    = (const int*)d_in[2];     // [T, K]
    const float* w1     = (const float*)d_in[3];   // [E, H, 2F]
    const float* b1     = (const float*)d_in[4];   // [E, 2F]
    const float* w2     = (const float*)d_in[5];   // [E, F, H]
    const float* b2     = (const float*)d_in[6];   // [E, H]
    float* out = (float*)d_out;                    // [T, H]

    int n = T_TOK * H_DIM;
    k_init<<<(n + 255) / 256, 256>>>(out);
    k_build<<<(TK + 255) / 256, 256>>>(ids);
    k_tilemap<<<1, 32>>>();
    k_gemm1<<<dim3(N1 / BN, MAX_TILES), 256>>>(hidden, w1, b1);
    k_gemm2<<<dim3(H_DIM / BN, MAX_TILES), 256>>>(w2, b2, tw, out);
}

// round 10
// speedup vs baseline: 3.5913x; 3.5872x over previous
#include <cuda_runtime.h>
#include <cstdint>

// Problem constants
#define T_TOK 16384
#define H_DIM 1024
#define E_NUM 16
#define F_DIM 2048
#define K_TOP 2
#define TK    (T_TOK * K_TOP)   // 32768
#define N1    (2 * F_DIM)       // 4096
#define BM 128
#define BN 128
#define KC 32
#define MAX_TILES (TK / BM + E_NUM)

// smem layout (float offsets)
#define SM_SLOT 0
#define SM_A    128
#define A_STRIDE 36
#define A_BUF   (BM * A_STRIDE)          // 4608 floats
#define SM_B    (SM_A + 2 * A_BUF)       // 9344
#define B_STRIDE 136
#define B_BUF   (KC * B_STRIDE)          // 4352
#define SMEM_FLOATS (SM_B + 2 * B_BUF)   // 18048
#define SMEM_BYTES  (SMEM_FLOATS * 4)    // 72192

// -------- device scratch (allocation-free contract) --------
__device__ int   g_counts[E_NUM];
__device__ int   g_slots[E_NUM * TK];
__device__ int   g_numTiles;
__device__ int   g_tileE[MAX_TILES + 8];
__device__ int   g_tileRow[MAX_TILES + 8];
__device__ float g_inter[(size_t)TK * F_DIM];            // 256 MB (tf32-rounded)
__device__ float g_w1[(size_t)E_NUM * H_DIM * N1];       // 256 MB tf32 W1
__device__ float g_w2[(size_t)E_NUM * F_DIM * H_DIM];    // 128 MB tf32 W2
__device__ float g_hid[(size_t)T_TOK * H_DIM];           // 64 MB tf32 hidden

// -------- helpers --------
__device__ __forceinline__ uint32_t smem_u32(const void* p) {
    uint32_t a;
    asm("{ .reg .u64 t; cvta.to.shared.u64 t, %1; cvt.u32.u64 %0, t; }" : "=r"(a) : "l"(p));
    return a;
}
__device__ __forceinline__ uint32_t f2tf(float x) {
    uint32_t r;
    asm("cvt.rna.tf32.f32 %0, %1;" : "=r"(r) : "f"(x));
    return r;
}
__device__ __forceinline__ void cp16(uint32_t dst, const float* src) {
    asm volatile("cp.async.ca.shared.global [%0], [%1], 16;" :: "r"(dst), "l"(src) : "memory");
}
#define CP_COMMIT() asm volatile("cp.async.commit_group;" ::: "memory")
#define CP_WAIT(n)  asm volatile("cp.async.wait_group %0;" :: "n"(n) : "memory")

__device__ __forceinline__ void mma8(float c[4], const uint32_t a[4], const uint32_t b[2]) {
    asm volatile(
        "mma.sync.aligned.m16n8k8.row.col.f32.tf32.tf32.f32 "
        "{%0,%1,%2,%3}, {%4,%5,%6,%7}, {%8,%9}, {%0,%1,%2,%3};"
        : "+f"(c[0]), "+f"(c[1]), "+f"(c[2]), "+f"(c[3])
        : "r"(a[0]), "r"(a[1]), "r"(a[2]), "r"(a[3]), "r"(b[0]), "r"(b[1]));
}

// -------- setup kernels --------
__global__ void k_init(float* __restrict__ out) {
    int i = blockIdx.x * blockDim.x + threadIdx.x;
    if (i < T_TOK * H_DIM) out[i] = 0.0f;
    if (i < E_NUM) g_counts[i] = 0;
}
__global__ void k_build(const int* __restrict__ topk_ids) {
    int i = blockIdx.x * blockDim.x + threadIdx.x;
    if (i < TK) {
        int e = topk_ids[i];
        int pos = atomicAdd(&g_counts[e], 1);
        g_slots[e * TK + pos] = i;
    }
}
__global__ void k_tilemap() {
    if (threadIdx.x == 0 && blockIdx.x == 0) {
        int idx = 0;
        for (int e = 0; e < E_NUM; e++) {
            int c = g_counts[e];
            for (int r = 0; r < c; r += BM) { g_tileE[idx] = e; g_tileRow[idx] = r; idx++; }
        }
        g_numTiles = idx;
    }
}
// RNE round fp32 -> tf32 (vectorized)
__global__ void k_round(const float* __restrict__ s, float* __restrict__ d, int n4) {
    int i = blockIdx.x * blockDim.x + threadIdx.x;
    if (i < n4) {
        float4 v = ((const float4*)s)[i];
        ((uint4*)d)[i] = make_uint4(f2tf(v.x), f2tf(v.y), f2tf(v.z), f2tf(v.w));
    }
}

// ================= GEMM1: hidden @ W1[e] + b1, swiglu -> g_inter =================
__global__ void __launch_bounds__(256, 2) k_gemm1(const float* __restrict__ bias)
{
    extern __shared__ float sm[];
    int tileIdx = blockIdx.y;
    if (tileIdx >= g_numTiles) return;
    int e = g_tileE[tileIdx], rowStart = g_tileRow[tileIdx];
    int rowsHere = min(BM, g_counts[e] - rowStart);
    int n0 = blockIdx.x * BN;
    int tid = threadIdx.x;

    int* sSlot = (int*)sm;
    if (tid < BM)
        sSlot[tid] = (tid < rowsHere) ? g_slots[e * TK + rowStart + tid]
                                      : g_slots[e * TK + rowStart];
    __syncthreads();

    // cp.async source pointers (A gathered by token; B weight strip)
    int arow = tid >> 3, aq = tid & 7;
    const float* aS0 = g_hid + (size_t)(sSlot[arow]      >> 1) * H_DIM + aq * 4;
    const float* aS1 = g_hid + (size_t)(sSlot[arow + 32] >> 1) * H_DIM + aq * 4;
    const float* aS2 = g_hid + (size_t)(sSlot[arow + 64] >> 1) * H_DIM + aq * 4;
    const float* aS3 = g_hid + (size_t)(sSlot[arow + 96] >> 1) * H_DIM + aq * 4;
    int brow = tid >> 5, bq = tid & 31;
    const float* Wb = g_w1 + (size_t)e * H_DIM * N1 + n0 + bq * 4;
    const float* bS0 = Wb + (size_t)(brow)      * N1;
    const float* bS1 = Wb + (size_t)(brow + 8)  * N1;
    const float* bS2 = Wb + (size_t)(brow + 16) * N1;
    const float* bS3 = Wb + (size_t)(brow + 24) * N1;

    uint32_t smU = smem_u32(sm);
    uint32_t aD = smU + (SM_A + arow * A_STRIDE) * 4 + aq * 16;
    uint32_t bD = smU + (SM_B + brow * B_STRIDE) * 4 + bq * 16;

    int lane = tid & 31, g_ = lane >> 2, tq = lane & 3;
    int wid = tid >> 5;
    int wm = (wid >> 2) * 64, wn = (wid & 3) * 32;

    float c[4][4][4];
    #pragma unroll
    for (int i = 0; i < 4; i++)
        #pragma unroll
        for (int j = 0; j < 4; j++)
            #pragma unroll
            for (int q = 0; q < 4; q++) c[i][j][q] = 0.0f;

#define ISSUE1(CH, BUF) do {                                               \
    size_t k0 = (size_t)(CH) * KC;                                         \
    uint32_t ad = aD + (BUF) * (A_BUF * 4);                                \
    cp16(ad,                       aS0 + k0);                              \
    cp16(ad + 32 * A_STRIDE * 4,   aS1 + k0);                              \
    cp16(ad + 64 * A_STRIDE * 4,   aS2 + k0);                              \
    cp16(ad + 96 * A_STRIDE * 4,   aS3 + k0);                              \
    uint32_t bd = bD + (BUF) * (B_BUF * 4);                                \
    size_t kb = k0 * N1;                                                   \
    cp16(bd,                       bS0 + kb);                              \
    cp16(bd + 8  * B_STRIDE * 4,   bS1 + kb);                              \
    cp16(bd + 16 * B_STRIDE * 4,   bS2 + kb);                              \
    cp16(bd + 24 * B_STRIDE * 4,   bS3 + kb); } while (0)

    const int NC = H_DIM / KC;   // 32
    ISSUE1(0, 0);
    CP_COMMIT();

    for (int ch = 0; ch < NC; ch++) {
        int buf = ch & 1;
        if (ch + 1 < NC) { ISSUE1(ch + 1, (ch + 1) & 1); CP_COMMIT(); CP_WAIT(1); }
        else             { CP_WAIT(0); }
        __syncthreads();
        const float* As = sm + SM_A + buf * A_BUF;
        const float* Bs = sm + SM_B + buf * B_BUF;
        #pragma unroll
        for (int kk = 0; kk < 4; kk++) {
            uint32_t af[4][4], bf[4][2];
            #pragma unroll
            for (int mt = 0; mt < 4; mt++) {
                int r = wm + mt * 16 + g_;
                af[mt][0] = __float_as_uint(As[r * A_STRIDE + kk * 8 + tq]);
                af[mt][1] = __float_as_uint(As[(r + 8) * A_STRIDE + kk * 8 + tq]);
                af[mt][2] = __float_as_uint(As[r * A_STRIDE + kk * 8 + tq + 4]);
                af[mt][3] = __float_as_uint(As[(r + 8) * A_STRIDE + kk * 8 + tq + 4]);
            }
            #pragma unroll
            for (int nt = 0; nt < 4; nt++) {
                int cl = wn + nt * 8 + g_;
                bf[nt][0] = __float_as_uint(Bs[(kk * 8 + tq) * B_STRIDE + cl]);
                bf[nt][1] = __float_as_uint(Bs[(kk * 8 + tq + 4) * B_STRIDE + cl]);
            }
            #pragma unroll
            for (int mt = 0; mt < 4; mt++)
                #pragma unroll
                for (int nt = 0; nt < 4; nt++)
                    mma8(c[mt][nt], af[mt], bf[nt]);
        }
        __syncthreads();
    }
#undef ISSUE1

    // epilogue: bias + swiglu, store tf32-rounded to g_inter
    const float* bp = bias + (size_t)e * N1 + n0;
    #pragma unroll
    for (int mt = 0; mt < 4; mt++) {
        #pragma unroll
        for (int half = 0; half < 2; half++) {
            int r = wm + mt * 16 + g_ + half * 8;
            if (r < rowsHere) {
                int slot = sSlot[r];
                float* orow = g_inter + (size_t)slot * F_DIM + (n0 >> 1) + (wn >> 1);
                #pragma unroll
                for (int nt = 0; nt < 4; nt++) {
                    int cb = wn + nt * 8 + 2 * tq;
                    float gt = c[mt][nt][half * 2 + 0] + bp[cb];
                    float up = c[mt][nt][half * 2 + 1] + bp[cb + 1];
                    gt = fminf(gt, 7.0f);
                    up = fminf(fmaxf(up, -7.0f), 7.0f);
                    float glu = gt / (1.0f + __expf(-1.702f * gt));
                    orow[nt * 4 + tq] = __uint_as_float(f2tf((up + 1.0f) * glu));
                }
            }
        }
    }
}

// ================= GEMM2: g_inter @ W2[e] + b2, weighted atomic combine =================
__global__ void __launch_bounds__(256, 2) k_gemm2(
    const float* __restrict__ bias, const float* __restrict__ tw,
    float* __restrict__ out)
{
    extern __shared__ float sm[];
    int tileIdx = blockIdx.y;
    if (tileIdx >= g_numTiles) return;
    int e = g_tileE[tileIdx], rowStart = g_tileRow[tileIdx];
    int rowsHere = min(BM, g_counts[e] - rowStart);
    int n0 = blockIdx.x * BN;
    int tid = threadIdx.x;

    int* sSlot = (int*)sm;
    if (tid < BM)
        sSlot[tid] = (tid < rowsHere) ? g_slots[e * TK + rowStart + tid]
                                      : g_slots[e * TK + rowStart];
    __syncthreads();

    int arow = tid >> 3, aq = tid & 7;
    const float* aS0 = g_inter + (size_t)sSlot[arow]      * F_DIM + aq * 4;
    const float* aS1 = g_inter + (size_t)sSlot[arow + 32] * F_DIM + aq * 4;
    const float* aS2 = g_inter + (size_t)sSlot[arow + 64] * F_DIM + aq * 4;
    const float* aS3 = g_inter + (size_t)sSlot[arow + 96] * F_DIM + aq * 4;
    int brow = tid >> 5, bq = tid & 31;
    const float* Wb = g_w2 + (size_t)e * F_DIM * H_DIM + n0 + bq * 4;
    const float* bS0 = Wb + (size_t)(brow)      * H_DIM;
    const float* bS1 = Wb + (size_t)(brow + 8)  * H_DIM;
    const float* bS2 = Wb + (size_t)(brow + 16) * H_DIM;
    const float* bS3 = Wb + (size_t)(brow + 24) * H_DIM;

    uint32_t smU = smem_u32(sm);
    uint32_t aD = smU + (SM_A + arow * A_STRIDE) * 4 + aq * 16;
    uint32_t bD = smU + (SM_B + brow * B_STRIDE) * 4 + bq * 16;

    int lane = tid & 31, g_ = lane >> 2, tq = lane & 3;
    int wid = tid >> 5;
    int wm = (wid >> 2) * 64, wn = (wid & 3) * 32;

    float c[4][4][4];
    #pragma unroll
    for (int i = 0; i < 4; i++)
        #pragma unroll
        for (int j = 0; j < 4; j++)
            #pragma unroll
            for (int q = 0; q < 4; q++) c[i][j][q] = 0.0f;

#define ISSUE2(CH, BUF) do {                                               \
    size_t k0 = (size_t)(CH) * KC;                                         \
    uint32_t ad = aD + (BUF) * (A_BUF * 4);                                \
    cp16(ad,                       aS0 + k0);                              \
    cp16(ad + 32 * A_STRIDE * 4,   aS1 + k0);                              \
    cp16(ad + 64 * A_STRIDE * 4,   aS2 + k0);                              \
    cp16(ad + 96 * A_STRIDE * 4,   aS3 + k0);                              \
    uint32_t bd = bD + (BUF) * (B_BUF * 4);                                \
    size_t kb = k0 * H_DIM;                                                \
    cp16(bd,                       bS0 + kb);                              \
    cp16(bd + 8  * B_STRIDE * 4,   bS1 + kb);                              \
    cp16(bd + 16 * B_STRIDE * 4,   bS2 + kb);                              \
    cp16(bd + 24 * B_STRIDE * 4,   bS3 + kb); } while (0)

    const int NC = F_DIM / KC;   // 64
    ISSUE2(0, 0);
    CP_COMMIT();

    for (int ch = 0; ch < NC; ch++) {
        int buf = ch & 1;
        if (ch + 1 < NC) { ISSUE2(ch + 1, (ch + 1) & 1); CP_COMMIT(); CP_WAIT(1); }
        else             { CP_WAIT(0); }
        __syncthreads();
        const float* As = sm + SM_A + buf * A_BUF;
        const float* Bs = sm + SM_B + buf * B_BUF;
        #pragma unroll
        for (int kk = 0; kk < 4; kk++) {
            uint32_t af[4][4], bf[4][2];
            #pragma unroll
            for (int mt = 0; mt < 4; mt++) {
                int r = wm + mt * 16 + g_;
                af[mt][0] = __float_as_uint(As[r * A_STRIDE + kk * 8 + tq]);
                af[mt][1] = __float_as_uint(As[(r + 8) * A_STRIDE + kk * 8 + tq]);
                af[mt][2] = __float_as_uint(As[r * A_STRIDE + kk * 8 + tq + 4]);
                af[mt][3] = __float_as_uint(As[(r + 8) * A_STRIDE + kk * 8 + tq + 4]);
            }
            #pragma unroll
            for (int nt = 0; nt < 4; nt++) {
                int cl = wn + nt * 8 + g_;
                bf[nt][0] = __float_as_uint(Bs[(kk * 8 + tq) * B_STRIDE + cl]);
                bf[nt][1] = __float_as_uint(Bs[(kk * 8 + tq + 4) * B_STRIDE + cl]);
            }
            #pragma unroll
            for (int mt = 0; mt < 4; mt++)
                #pragma unroll
                for (int nt = 0; nt < 4; nt++)
                    mma8(c[mt][nt], af[mt], bf[nt]);
        }
        __syncthreads();
    }
#undef ISSUE2

    // epilogue: bias, routing weight, atomic combine
    const float* bp = bias + (size_t)e * H_DIM + n0;
    #pragma unroll
    for (int mt = 0; mt < 4; mt++) {
        #pragma unroll
        for (int half = 0; half < 2; half++) {
            int r = wm + mt * 16 + g_ + half * 8;
            if (r < rowsHere) {
                int slot = sSlot[r];
                float w = tw[slot];
                float* orow = out + (size_t)(slot >> 1) * H_DIM + n0 + wn;
                #pragma unroll
                for (int nt = 0; nt < 4; nt++) {
                    int cb = nt * 8 + 2 * tq;
                    atomicAdd(orow + cb,     w * (c[mt][nt][half * 2 + 0] + bp[wn + cb]));
                    atomicAdd(orow + cb + 1, w * (c[mt][nt][half * 2 + 1] + bp[wn + cb + 1]));
                }
            }
        }
    }
}

extern "C" void kernel_launch(void* const* d_in, const int* in_sizes, int n_in,
                              void* d_out, int out_size) {
    const float* hidden = (const float*)d_in[0];   // [T, H]
    const float* tw     = (const float*)d_in[1];   // [T, K]
    const int*   ids    = (const int*)d_in[2];     // [T, K]
    const float* w1     = (const float*)d_in[3];   // [E, H, 2F]
    const float* b1     = (const float*)d_in[4];   // [E, 2F]
    const float* w2     = (const float*)d_in[5];   // [E, F, H]
    const float* b2     = (const float*)d_in[6];   // [E, H]
    float* out = (float*)d_out;                    // [T, H]

    cudaFuncSetAttribute(k_gemm1, cudaFuncAttributeMaxDynamicSharedMemorySize, SMEM_BYTES);
    cudaFuncSetAttribute(k_gemm2, cudaFuncAttributeMaxDynamicSharedMemorySize, SMEM_BYTES);

    float* d_w1t; cudaGetSymbolAddress((void**)&d_w1t, g_w1);
    float* d_w2t; cudaGetSymbolAddress((void**)&d_w2t, g_w2);
    float* d_hid; cudaGetSymbolAddress((void**)&d_hid, g_hid);

    int n = T_TOK * H_DIM;
    k_init<<<(n + 255) / 256, 256>>>(out);
    k_build<<<(TK + 255) / 256, 256>>>(ids);
    k_tilemap<<<1, 32>>>();
    // pre-round operands to tf32 (RNE)
    k_round<<<(E_NUM * H_DIM * N1 / 4 + 255) / 256, 256>>>(w1, d_w1t, E_NUM * H_DIM * N1 / 4);
    k_round<<<(E_NUM * F_DIM * H_DIM / 4 + 255) / 256, 256>>>(w2, d_w2t, E_NUM * F_DIM * H_DIM / 4);
    k_round<<<(T_TOK * H_DIM / 4 + 255) / 256, 256>>>(hidden, d_hid, T_TOK * H_DIM / 4);

    k_gemm1<<<dim3(N1 / BN, MAX_TILES), 256, SMEM_BYTES>>>(b1);
    k_gemm2<<<dim3(H_DIM / BN, MAX_TILES), 256, SMEM_BYTES>>>(b2, tw, out);
}

// round 11
// speedup vs baseline: 3.5943x; 1.0008x over previous
#include <cuda_runtime.h>
#include <cstdint>

// Problem constants
#define T_TOK 16384
#define H_DIM 1024
#define E_NUM 16
#define F_DIM 2048
#define K_TOP 2
#define TK    (T_TOK * K_TOP)   // 32768
#define N1    (2 * F_DIM)       // 4096
#define BM 128
#define BN 128
#define KC 32
#define MAX_TILES (TK / BM + E_NUM)

// smem layout (float offsets)
#define SM_SLOT 0
#define SM_A    128
#define A_STRIDE 36
#define A_BUF   (BM * A_STRIDE)          // 4608 floats
#define SM_B    (SM_A + 2 * A_BUF)       // 9344
#define B_STRIDE 136
#define B_BUF   (KC * B_STRIDE)          // 4352
#define SMEM_FLOATS (SM_B + 2 * B_BUF)   // 18048
#define SMEM_BYTES  (SMEM_FLOATS * 4)    // 72192

// -------- device scratch (allocation-free contract) --------
__device__ int   g_counts[E_NUM];
__device__ int   g_slots[E_NUM * TK];
__device__ int   g_numTiles;
__device__ int   g_tileE[MAX_TILES + 8];
__device__ int   g_tileRow[MAX_TILES + 8];
__device__ float g_inter[(size_t)TK * F_DIM];            // 256 MB (tf32-rounded)
__device__ float g_w1[(size_t)E_NUM * H_DIM * N1];       // 256 MB tf32 W1
__device__ float g_w2[(size_t)E_NUM * F_DIM * H_DIM];    // 128 MB tf32 W2
__device__ float g_hid[(size_t)T_TOK * H_DIM];           // 64 MB tf32 hidden

// -------- helpers --------
__device__ __forceinline__ uint32_t smem_u32(const void* p) {
    uint32_t a;
    asm("{ .reg .u64 t; cvta.to.shared.u64 t, %1; cvt.u32.u64 %0, t; }" : "=r"(a) : "l"(p));
    return a;
}
__device__ __forceinline__ uint32_t f2tf(float x) {
    uint32_t r;
    asm("cvt.rna.tf32.f32 %0, %1;" : "=r"(r) : "f"(x));
    return r;
}
__device__ __forceinline__ void cp16(uint32_t dst, const float* src) {
    asm volatile("cp.async.ca.shared.global [%0], [%1], 16;" :: "r"(dst), "l"(src) : "memory");
}
#define CP_COMMIT() asm volatile("cp.async.commit_group;" ::: "memory")
#define CP_WAIT(n)  asm volatile("cp.async.wait_group %0;" :: "n"(n) : "memory")

__device__ __forceinline__ void mma8(float c[4], const uint32_t a[4], const uint32_t b[2]) {
    asm volatile(
        "mma.sync.aligned.m16n8k8.row.col.f32.tf32.tf32.f32 "
        "{%0,%1,%2,%3}, {%4,%5,%6,%7}, {%8,%9}, {%0,%1,%2,%3};"
        : "+f"(c[0]), "+f"(c[1]), "+f"(c[2]), "+f"(c[3])
        : "r"(a[0]), "r"(a[1]), "r"(a[2]), "r"(a[3]), "r"(b[0]), "r"(b[1]));
}

// -------- setup kernels --------
__global__ void k_init(float* __restrict__ out) {
    int i = blockIdx.x * blockDim.x + threadIdx.x;
    if (i < T_TOK * H_DIM) out[i] = 0.0f;
    if (i < E_NUM) g_counts[i] = 0;
}
__global__ void k_build(const int* __restrict__ topk_ids) {
    int i = blockIdx.x * blockDim.x + threadIdx.x;
    if (i < TK) {
        int e = topk_ids[i];
        int pos = atomicAdd(&g_counts[e], 1);
        g_slots[e * TK + pos] = i;
    }
}
__global__ void k_tilemap() {
    if (threadIdx.x == 0 && blockIdx.x == 0) {
        int idx = 0;
        for (int e = 0; e < E_NUM; e++) {
            int c = g_counts[e];
            for (int r = 0; r < c; r += BM) { g_tileE[idx] = e; g_tileRow[idx] = r; idx++; }
        }
        g_numTiles = idx;
    }
}
// RNE round fp32 -> tf32 (vectorized)
__global__ void k_round(const float* __restrict__ s, float* __restrict__ d, int n4) {
    int i = blockIdx.x * blockDim.x + threadIdx.x;
    if (i < n4) {
        float4 v = ((const float4*)s)[i];
        ((uint4*)d)[i] = make_uint4(f2tf(v.x), f2tf(v.y), f2tf(v.z), f2tf(v.w));
    }
}

// ================= GEMM1: hidden @ W1[e] + b1, swiglu -> g_inter =================
__global__ void __launch_bounds__(256, 2) k_gemm1(const float* __restrict__ bias)
{
    extern __shared__ float sm[];
    int tileIdx = blockIdx.y;
    if (tileIdx >= g_numTiles) return;
    int e = g_tileE[tileIdx], rowStart = g_tileRow[tileIdx];
    int rowsHere = min(BM, g_counts[e] - rowStart);
    int n0 = blockIdx.x * BN;
    int tid = threadIdx.x;

    int* sSlot = (int*)sm;
    if (tid < BM)
        sSlot[tid] = (tid < rowsHere) ? g_slots[e * TK + rowStart + tid]
                                      : g_slots[e * TK + rowStart];
    __syncthreads();

    // cp.async source pointers (A gathered by token; B weight strip)
    int arow = tid >> 3, aq = tid & 7;
    const float* aS0 = g_hid + (size_t)(sSlot[arow]      >> 1) * H_DIM + aq * 4;
    const float* aS1 = g_hid + (size_t)(sSlot[arow + 32] >> 1) * H_DIM + aq * 4;
    const float* aS2 = g_hid + (size_t)(sSlot[arow + 64] >> 1) * H_DIM + aq * 4;
    const float* aS3 = g_hid + (size_t)(sSlot[arow + 96] >> 1) * H_DIM + aq * 4;
    int brow = tid >> 5, bq = tid & 31;
    const float* Wb = g_w1 + (size_t)e * H_DIM * N1 + n0 + bq * 4;
    const float* bS0 = Wb + (size_t)(brow)      * N1;
    const float* bS1 = Wb + (size_t)(brow + 8)  * N1;
    const float* bS2 = Wb + (size_t)(brow + 16) * N1;
    const float* bS3 = Wb + (size_t)(brow + 24) * N1;

    uint32_t smU = smem_u32(sm);
    uint32_t aD = smU + (SM_A + arow * A_STRIDE) * 4 + aq * 16;
    uint32_t bD = smU + (SM_B + brow * B_STRIDE) * 4 + bq * 16;

    int lane = tid & 31, g_ = lane >> 2, tq = lane & 3;
    int wid = tid >> 5;
    int wm = (wid >> 2) * 64, wn = (wid & 3) * 32;

    float c[4][4][4];
    #pragma unroll
    for (int i = 0; i < 4; i++)
        #pragma unroll
        for (int j = 0; j < 4; j++)
            #pragma unroll
            for (int q = 0; q < 4; q++) c[i][j][q] = 0.0f;

#define ISSUE1(CH, BUF) do {                                               \
    size_t k0 = (size_t)(CH) * KC;                                         \
    uint32_t ad = aD + (BUF) * (A_BUF * 4);                                \
    cp16(ad,                       aS0 + k0);                              \
    cp16(ad + 32 * A_STRIDE * 4,   aS1 + k0);                              \
    cp16(ad + 64 * A_STRIDE * 4,   aS2 + k0);                              \
    cp16(ad + 96 * A_STRIDE * 4,   aS3 + k0);                              \
    uint32_t bd = bD + (BUF) * (B_BUF * 4);                                \
    size_t kb = k0 * N1;                                                   \
    cp16(bd,                       bS0 + kb);                              \
    cp16(bd + 8  * B_STRIDE * 4,   bS1 + kb);                              \
    cp16(bd + 16 * B_STRIDE * 4,   bS2 + kb);                              \
    cp16(bd + 24 * B_STRIDE * 4,   bS3 + kb); } while (0)

    const int NC = H_DIM / KC;   // 32
    ISSUE1(0, 0);
    CP_COMMIT();

    for (int ch = 0; ch < NC; ch++) {
        int buf = ch & 1;
        if (ch + 1 < NC) { ISSUE1(ch + 1, (ch + 1) & 1); CP_COMMIT(); CP_WAIT(1); }
        else             { CP_WAIT(0); }
        __syncthreads();
        const float* As = sm + SM_A + buf * A_BUF;
        const float* Bs = sm + SM_B + buf * B_BUF;
        #pragma unroll
        for (int kk = 0; kk < 4; kk++) {
            uint32_t af[4][4], bf[4][2];
            #pragma unroll
            for (int mt = 0; mt < 4; mt++) {
                int r = wm + mt * 16 + g_;
                af[mt][0] = __float_as_uint(As[r * A_STRIDE + kk * 8 + tq]);
                af[mt][1] = __float_as_uint(As[(r + 8) * A_STRIDE + kk * 8 + tq]);
                af[mt][2] = __float_as_uint(As[r * A_STRIDE + kk * 8 + tq + 4]);
                af[mt][3] = __float_as_uint(As[(r + 8) * A_STRIDE + kk * 8 + tq + 4]);
            }
            #pragma unroll
            for (int nt = 0; nt < 4; nt++) {
                int cl = wn + nt * 8 + g_;
                bf[nt][0] = __float_as_uint(Bs[(kk * 8 + tq) * B_STRIDE + cl]);
                bf[nt][1] = __float_as_uint(Bs[(kk * 8 + tq + 4) * B_STRIDE + cl]);
            }
            #pragma unroll
            for (int mt = 0; mt < 4; mt++)
                #pragma unroll
                for (int nt = 0; nt < 4; nt++)
                    mma8(c[mt][nt], af[mt], bf[nt]);
        }
        __syncthreads();
    }
#undef ISSUE1

    // epilogue: bias + swiglu, store tf32-rounded to g_inter
    const float* bp = bias + (size_t)e * N1 + n0;
    #pragma unroll
    for (int mt = 0; mt < 4; mt++) {
        #pragma unroll
        for (int half = 0; half < 2; half++) {
            int r = wm + mt * 16 + g_ + half * 8;
            if (r < rowsHere) {
                int slot = sSlot[r];
                float* orow = g_inter + (size_t)slot * F_DIM + (n0 >> 1) + (wn >> 1);
                #pragma unroll
                for (int nt = 0; nt < 4; nt++) {
                    int cb = wn + nt * 8 + 2 * tq;
                    float gt = c[mt][nt][half * 2 + 0] + bp[cb];
                    float up = c[mt][nt][half * 2 + 1] + bp[cb + 1];
                    gt = fminf(gt, 7.0f);
                    up = fminf(fmaxf(up, -7.0f), 7.0f);
                    float glu = gt / (1.0f + __expf(-1.702f * gt));
                    orow[nt * 4 + tq] = __uint_as_float(f2tf((up + 1.0f) * glu));
                }
            }
        }
    }
}

// ================= GEMM2: g_inter @ W2[e] + b2, weighted atomic combine =================
__global__ void __launch_bounds__(256, 2) k_gemm2(
    const float* __restrict__ bias, const float* __restrict__ tw,
    float* __restrict__ out)
{
    extern __shared__ float sm[];
    int tileIdx = blockIdx.y;
    if (tileIdx >= g_numTiles) return;
    int e = g_tileE[tileIdx], rowStart = g_tileRow[tileIdx];
    int rowsHere = min(BM, g_counts[e] - rowStart);
    int n0 = blockIdx.x * BN;
    int tid = threadIdx.x;

    int* sSlot = (int*)sm;
    if (tid < BM)
        sSlot[tid] = (tid < rowsHere) ? g_slots[e * TK + rowStart + tid]
                                      : g_slots[e * TK + rowStart];
    __syncthreads();

    int arow = tid >> 3, aq = tid & 7;
    const float* aS0 = g_inter + (size_t)sSlot[arow]      * F_DIM + aq * 4;
    const float* aS1 = g_inter + (size_t)sSlot[arow + 32] * F_DIM + aq * 4;
    const float* aS2 = g_inter + (size_t)sSlot[arow + 64] * F_DIM + aq * 4;
    const float* aS3 = g_inter + (size_t)sSlot[arow + 96] * F_DIM + aq * 4;
    int brow = tid >> 5, bq = tid & 31;
    const float* Wb = g_w2 + (size_t)e * F_DIM * H_DIM + n0 + bq * 4;
    const float* bS0 = Wb + (size_t)(brow)      * H_DIM;
    const float* bS1 = Wb + (size_t)(brow + 8)  * H_DIM;
    const float* bS2 = Wb + (size_t)(brow + 16) * H_DIM;
    const float* bS3 = Wb + (size_t)(brow + 24) * H_DIM;

    uint32_t smU = smem_u32(sm);
    uint32_t aD = smU + (SM_A + arow * A_STRIDE) * 4 + aq * 16;
    uint32_t bD = smU + (SM_B + brow * B_STRIDE) * 4 + bq * 16;

    int lane = tid & 31, g_ = lane >> 2, tq = lane & 3;
    int wid = tid >> 5;
    int wm = (wid >> 2) * 64, wn = (wid & 3) * 32;

    float c[4][4][4];
    #pragma unroll
    for (int i = 0; i < 4; i++)
        #pragma unroll
        for (int j = 0; j < 4; j++)
            #pragma unroll
            for (int q = 0; q < 4; q++) c[i][j][q] = 0.0f;

#define ISSUE2(CH, BUF) do {                                               \
    size_t k0 = (size_t)(CH) * KC;                                         \
    uint32_t ad = aD + (BUF) * (A_BUF * 4);                                \
    cp16(ad,                       aS0 + k0);                              \
    cp16(ad + 32 * A_STRIDE * 4,   aS1 + k0);                              \
    cp16(ad + 64 * A_STRIDE * 4,   aS2 + k0);                              \
    cp16(ad + 96 * A_STRIDE * 4,   aS3 + k0);                              \
    uint32_t bd = bD + (BUF) * (B_BUF * 4);                                \
    size_t kb = k0 * H_DIM;                                                \
    cp16(bd,                       bS0 + kb);                              \
    cp16(bd + 8  * B_STRIDE * 4,   bS1 + kb);                              \
    cp16(bd + 16 * B_STRIDE * 4,   bS2 + kb);                              \
    cp16(bd + 24 * B_STRIDE * 4,   bS3 + kb); } while (0)

    const int NC = F_DIM / KC;   // 64
    ISSUE2(0, 0);
    CP_COMMIT();

    for (int ch = 0; ch < NC; ch++) {
        int buf = ch & 1;
        if (ch + 1 < NC) { ISSUE2(ch + 1, (ch + 1) & 1); CP_COMMIT(); CP_WAIT(1); }
        else             { CP_WAIT(0); }
        __syncthreads();
        const float* As = sm + SM_A + buf * A_BUF;
        const float* Bs = sm + SM_B + buf * B_BUF;
        #pragma unroll
        for (int kk = 0; kk < 4; kk++) {
            uint32_t af[4][4], bf[4][2];
            #pragma unroll
            for (int mt = 0; mt < 4; mt++) {
                int r = wm + mt * 16 + g_;
                af[mt][0] = __float_as_uint(As[r * A_STRIDE + kk * 8 + tq]);
                af[mt][1] = __float_as_uint(As[(r + 8) * A_STRIDE + kk * 8 + tq]);
                af[mt][2] = __float_as_uint(As[r * A_STRIDE + kk * 8 + tq + 4]);
                af[mt][3] = __float_as_uint(As[(r + 8) * A_STRIDE + kk * 8 + tq + 4]);
            }
            #pragma unroll
            for (int nt = 0; nt < 4; nt++) {
                int cl = wn + nt * 8 + g_;
                bf[nt][0] = __float_as_uint(Bs[(kk * 8 + tq) * B_STRIDE + cl]);
                bf[nt][1] = __float_as_uint(Bs[(kk * 8 + tq + 4) * B_STRIDE + cl]);
            }
            #pragma unroll
            for (int mt = 0; mt < 4; mt++)
                #pragma unroll
                for (int nt = 0; nt < 4; nt++)
                    mma8(c[mt][nt], af[mt], bf[nt]);
        }
        __syncthreads();
    }
#undef ISSUE2

    // epilogue: bias, routing weight, atomic combine
    const float* bp = bias + (size_t)e * H_DIM + n0;
    #pragma unroll
    for (int mt = 0; mt < 4; mt++) {
        #pragma unroll
        for (int half = 0; half < 2; half++) {
            int r = wm + mt * 16 + g_ + half * 8;
            if (r < rowsHere) {
                int slot = sSlot[r];
                float w = tw[slot];
                float* orow = out + (size_t)(slot >> 1) * H_DIM + n0 + wn;
                #pragma unroll
                for (int nt = 0; nt < 4; nt++) {
                    int cb = nt * 8 + 2 * tq;
                    atomicAdd(orow + cb,     w * (c[mt][nt][half * 2 + 0] + bp[wn + cb]));
                    atomicAdd(orow + cb + 1, w * (c[mt][nt][half * 2 + 1] + bp[wn + cb + 1]));
                }
            }
        }
    }
}

extern "C" void kernel_launch(void* const* d_in, const int* in_sizes, int n_in,
                              void* d_out, int out_size) {
    const float* hidden = (const float*)d_in[0];   // [T, H]
    const float* tw     = (const float*)d_in[1];   // [T, K]
    const int*   ids    = (const int*)d_in[2];     // [T, K]
    const float* w1     = (const float*)d_in[3];   // [E, H, 2F]
    const float* b1     = (const float*)d_in[4];   // [E, 2F]
    const float* w2     = (const float*)d_in[5];   // [E, F, H]
    const float* b2     = (const float*)d_in[6];   // [E, H]
    float* out = (float*)d_out;                    // [T, H]

    cudaFuncSetAttribute(k_gemm1, cudaFuncAttributeMaxDynamicSharedMemorySize, SMEM_BYTES);
    cudaFuncSetAttribute(k_gemm2, cudaFuncAttributeMaxDynamicSharedMemorySize, SMEM_BYTES);

    float* d_w1t; cudaGetSymbolAddress((void**)&d_w1t, g_w1);
    float* d_w2t; cudaGetSymbolAddress((void**)&d_w2t, g_w2);
    float* d_hid; cudaGetSymbolAddress((void**)&d_hid, g_hid);

    int n = T_TOK * H_DIM;
    k_init<<<(n + 255) / 256, 256>>>(out);
    k_build<<<(TK + 255) / 256, 256>>>(ids);
    k_tilemap<<<1, 32>>>();
    // pre-round operands to tf32 (RNE)
    k_round<<<(E_NUM * H_DIM * N1 / 4 + 255) / 256, 256>>>(w1, d_w1t, E_NUM * H_DIM * N1 / 4);
    k_round<<<(E_NUM * F_DIM * H_DIM / 4 + 255) / 256, 256>>>(w2, d_w2t, E_NUM * F_DIM * H_DIM / 4);
    k_round<<<(T_TOK * H_DIM / 4 + 255) / 256, 256>>>(hidden, d_hid, T_TOK * H_DIM / 4);

    k_gemm1<<<dim3(N1 / BN, MAX_TILES), 256, SMEM_BYTES>>>(b1);
    k_gemm2<<<dim3(H_DIM / BN, MAX_TILES), 256, SMEM_BYTES>>>(b2, tw, out);
}

// round 12
// speedup vs baseline: 3.5958x; 1.0004x over previous
#include <cuda_runtime.h>
#include <cstdint>

// Problem constants
#define T_TOK 16384
#define H_DIM 1024
#define E_NUM 16
#define F_DIM 2048
#define K_TOP 2
#define TK    (T_TOK * K_TOP)   // 32768
#define N1    (2 * F_DIM)       // 4096
#define BM 128
#define BN 128
#define KC 32
#define MAX_TILES (TK / BM + E_NUM)

// smem layout (float offsets)
#define SM_SLOT 0
#define SM_A    128
#define A_STRIDE 36
#define A_BUF   (BM * A_STRIDE)          // 4608 floats
#define SM_B    (SM_A + 2 * A_BUF)       // 9344
#define B_STRIDE 136
#define B_BUF   (KC * B_STRIDE)          // 4352
#define SMEM_FLOATS (SM_B + 2 * B_BUF)   // 18048
#define SMEM_BYTES  (SMEM_FLOATS * 4)    // 72192

// -------- device scratch (allocation-free contract) --------
__device__ int   g_counts[E_NUM];
__device__ int   g_slots[E_NUM * TK];
__device__ int   g_numTiles;
__device__ int   g_tileE[MAX_TILES + 8];
__device__ int   g_tileRow[MAX_TILES + 8];
__device__ float g_inter[(size_t)TK * F_DIM];            // 256 MB (tf32-rounded)
__device__ float g_w1[(size_t)E_NUM * H_DIM * N1];       // 256 MB tf32 W1
__device__ float g_w2[(size_t)E_NUM * F_DIM * H_DIM];    // 128 MB tf32 W2
__device__ float g_hid[(size_t)T_TOK * H_DIM];           // 64 MB tf32 hidden

// -------- helpers --------
__device__ __forceinline__ uint32_t smem_u32(const void* p) {
    uint32_t a;
    asm("{ .reg .u64 t; cvta.to.shared.u64 t, %1; cvt.u32.u64 %0, t; }" : "=r"(a) : "l"(p));
    return a;
}
__device__ __forceinline__ uint32_t f2tf(float x) {
    uint32_t r;
    asm("cvt.rna.tf32.f32 %0, %1;" : "=r"(r) : "f"(x));
    return r;
}
__device__ __forceinline__ void cp16(uint32_t dst, const float* src) {
    asm volatile("cp.async.ca.shared.global [%0], [%1], 16;" :: "r"(dst), "l"(src) : "memory");
}
#define CP_COMMIT() asm volatile("cp.async.commit_group;" ::: "memory")
#define CP_WAIT(n)  asm volatile("cp.async.wait_group %0;" :: "n"(n) : "memory")

__device__ __forceinline__ void mma8(float c[4], const uint32_t a[4], const uint32_t b[2]) {
    asm volatile(
        "mma.sync.aligned.m16n8k8.row.col.f32.tf32.tf32.f32 "
        "{%0,%1,%2,%3}, {%4,%5,%6,%7}, {%8,%9}, {%0,%1,%2,%3};"
        : "+f"(c[0]), "+f"(c[1]), "+f"(c[2]), "+f"(c[3])
        : "r"(a[0]), "r"(a[1]), "r"(a[2]), "r"(a[3]), "r"(b[0]), "r"(b[1]));
}

// -------- setup kernels --------
__global__ void k_init(float* __restrict__ out) {
    int i = blockIdx.x * blockDim.x + threadIdx.x;
    if (i < T_TOK * H_DIM) out[i] = 0.0f;
    if (i < E_NUM) g_counts[i] = 0;
}
__global__ void k_build(const int* __restrict__ topk_ids) {
    int i = blockIdx.x * blockDim.x + threadIdx.x;
    if (i < TK) {
        int e = topk_ids[i];
        int pos = atomicAdd(&g_counts[e], 1);
        g_slots[e * TK + pos] = i;
    }
}
__global__ void k_tilemap() {
    if (threadIdx.x == 0 && blockIdx.x == 0) {
        int idx = 0;
        for (int e = 0; e < E_NUM; e++) {
            int c = g_counts[e];
            for (int r = 0; r < c; r += BM) { g_tileE[idx] = e; g_tileRow[idx] = r; idx++; }
        }
        g_numTiles = idx;
    }
}
// RNE round fp32 -> tf32 (vectorized)
__global__ void k_round(const float* __restrict__ s, float* __restrict__ d, int n4) {
    int i = blockIdx.x * blockDim.x + threadIdx.x;
    if (i < n4) {
        float4 v = ((const float4*)s)[i];
        ((uint4*)d)[i] = make_uint4(f2tf(v.x), f2tf(v.y), f2tf(v.z), f2tf(v.w));
    }
}

// ================= GEMM1: hidden @ W1[e] + b1, swiglu -> g_inter =================
__global__ void __launch_bounds__(256, 2) k_gemm1(const float* __restrict__ bias)
{
    extern __shared__ float sm[];
    int tileIdx = blockIdx.y;
    if (tileIdx >= g_numTiles) return;
    int e = g_tileE[tileIdx], rowStart = g_tileRow[tileIdx];
    int rowsHere = min(BM, g_counts[e] - rowStart);
    int n0 = blockIdx.x * BN;
    int tid = threadIdx.x;

    int* sSlot = (int*)sm;
    if (tid < BM)
        sSlot[tid] = (tid < rowsHere) ? g_slots[e * TK + rowStart + tid]
                                      : g_slots[e * TK + rowStart];
    __syncthreads();

    // cp.async source pointers (A gathered by token; B weight strip)
    int arow = tid >> 3, aq = tid & 7;
    const float* aS0 = g_hid + (size_t)(sSlot[arow]      >> 1) * H_DIM + aq * 4;
    const float* aS1 = g_hid + (size_t)(sSlot[arow + 32] >> 1) * H_DIM + aq * 4;
    const float* aS2 = g_hid + (size_t)(sSlot[arow + 64] >> 1) * H_DIM + aq * 4;
    const float* aS3 = g_hid + (size_t)(sSlot[arow + 96] >> 1) * H_DIM + aq * 4;
    int brow = tid >> 5, bq = tid & 31;
    const float* Wb = g_w1 + (size_t)e * H_DIM * N1 + n0 + bq * 4;
    const float* bS0 = Wb + (size_t)(brow)      * N1;
    const float* bS1 = Wb + (size_t)(brow + 8)  * N1;
    const float* bS2 = Wb + (size_t)(brow + 16) * N1;
    const float* bS3 = Wb + (size_t)(brow + 24) * N1;

    uint32_t smU = smem_u32(sm);
    uint32_t aD = smU + (SM_A + arow * A_STRIDE) * 4 + aq * 16;
    uint32_t bD = smU + (SM_B + brow * B_STRIDE) * 4 + bq * 16;

    int lane = tid & 31, g_ = lane >> 2, tq = lane & 3;
    int wid = tid >> 5;
    int wm = (wid >> 2) * 64, wn = (wid & 3) * 32;

    float c[4][4][4];
    #pragma unroll
    for (int i = 0; i < 4; i++)
        #pragma unroll
        for (int j = 0; j < 4; j++)
            #pragma unroll
            for (int q = 0; q < 4; q++) c[i][j][q] = 0.0f;

#define ISSUE1(CH, BUF) do {                                               \
    size_t k0 = (size_t)(CH) * KC;                                         \
    uint32_t ad = aD + (BUF) * (A_BUF * 4);                                \
    cp16(ad,                       aS0 + k0);                              \
    cp16(ad + 32 * A_STRIDE * 4,   aS1 + k0);                              \
    cp16(ad + 64 * A_STRIDE * 4,   aS2 + k0);                              \
    cp16(ad + 96 * A_STRIDE * 4,   aS3 + k0);                              \
    uint32_t bd = bD + (BUF) * (B_BUF * 4);                                \
    size_t kb = k0 * N1;                                                   \
    cp16(bd,                       bS0 + kb);                              \
    cp16(bd + 8  * B_STRIDE * 4,   bS1 + kb);                              \
    cp16(bd + 16 * B_STRIDE * 4,   bS2 + kb);                              \
    cp16(bd + 24 * B_STRIDE * 4,   bS3 + kb); } while (0)

    const int NC = H_DIM / KC;   // 32
    ISSUE1(0, 0);
    CP_COMMIT();

    for (int ch = 0; ch < NC; ch++) {
        int buf = ch & 1;
        if (ch + 1 < NC) { ISSUE1(ch + 1, (ch + 1) & 1); CP_COMMIT(); CP_WAIT(1); }
        else             { CP_WAIT(0); }
        __syncthreads();
        const float* As = sm + SM_A + buf * A_BUF;
        const float* Bs = sm + SM_B + buf * B_BUF;
        #pragma unroll
        for (int kk = 0; kk < 4; kk++) {
            uint32_t af[4][4], bf[4][2];
            #pragma unroll
            for (int mt = 0; mt < 4; mt++) {
                int r = wm + mt * 16 + g_;
                af[mt][0] = __float_as_uint(As[r * A_STRIDE + kk * 8 + tq]);
                af[mt][1] = __float_as_uint(As[(r + 8) * A_STRIDE + kk * 8 + tq]);
                af[mt][2] = __float_as_uint(As[r * A_STRIDE + kk * 8 + tq + 4]);
                af[mt][3] = __float_as_uint(As[(r + 8) * A_STRIDE + kk * 8 + tq + 4]);
            }
            #pragma unroll
            for (int nt = 0; nt < 4; nt++) {
                int cl = wn + nt * 8 + g_;
                bf[nt][0] = __float_as_uint(Bs[(kk * 8 + tq) * B_STRIDE + cl]);
                bf[nt][1] = __float_as_uint(Bs[(kk * 8 + tq + 4) * B_STRIDE + cl]);
            }
            #pragma unroll
            for (int mt = 0; mt < 4; mt++)
                #pragma unroll
                for (int nt = 0; nt < 4; nt++)
                    mma8(c[mt][nt], af[mt], bf[nt]);
        }
        __syncthreads();
    }
#undef ISSUE1

    // epilogue: bias + swiglu, store tf32-rounded to g_inter
    const float* bp = bias + (size_t)e * N1 + n0;
    #pragma unroll
    for (int mt = 0; mt < 4; mt++) {
        #pragma unroll
        for (int half = 0; half < 2; half++) {
            int r = wm + mt * 16 + g_ + half * 8;
            if (r < rowsHere) {
                int slot = sSlot[r];
                float* orow = g_inter + (size_t)slot * F_DIM + (n0 >> 1) + (wn >> 1);
                #pragma unroll
                for (int nt = 0; nt < 4; nt++) {
                    int cb = wn + nt * 8 + 2 * tq;
                    float gt = c[mt][nt][half * 2 + 0] + bp[cb];
                    float up = c[mt][nt][half * 2 + 1] + bp[cb + 1];
                    gt = fminf(gt, 7.0f);
                    up = fminf(fmaxf(up, -7.0f), 7.0f);
                    float glu = gt / (1.0f + __expf(-1.702f * gt));
                    orow[nt * 4 + tq] = __uint_as_float(f2tf((up + 1.0f) * glu));
                }
            }
        }
    }
}

// ================= GEMM2: g_inter @ W2[e] + b2, weighted atomic combine =================
__global__ void __launch_bounds__(256, 2) k_gemm2(
    const float* __restrict__ bias, const float* __restrict__ tw,
    float* __restrict__ out)
{
    extern __shared__ float sm[];
    int tileIdx = blockIdx.y;
    if (tileIdx >= g_numTiles) return;
    int e = g_tileE[tileIdx], rowStart = g_tileRow[tileIdx];
    int rowsHere = min(BM, g_counts[e] - rowStart);
    int n0 = blockIdx.x * BN;
    int tid = threadIdx.x;

    int* sSlot = (int*)sm;
    if (tid < BM)
        sSlot[tid] = (tid < rowsHere) ? g_slots[e * TK + rowStart + tid]
                                      : g_slots[e * TK + rowStart];
    __syncthreads();

    int arow = tid >> 3, aq = tid & 7;
    const float* aS0 = g_inter + (size_t)sSlot[arow]      * F_DIM + aq * 4;
    const float* aS1 = g_inter + (size_t)sSlot[arow + 32] * F_DIM + aq * 4;
    const float* aS2 = g_inter + (size_t)sSlot[arow + 64] * F_DIM + aq * 4;
    const float* aS3 = g_inter + (size_t)sSlot[arow + 96] * F_DIM + aq * 4;
    int brow = tid >> 5, bq = tid & 31;
    const float* Wb = g_w2 + (size_t)e * F_DIM * H_DIM + n0 + bq * 4;
    const float* bS0 = Wb + (size_t)(brow)      * H_DIM;
    const float* bS1 = Wb + (size_t)(brow + 8)  * H_DIM;
    const float* bS2 = Wb + (size_t)(brow + 16) * H_DIM;
    const float* bS3 = Wb + (size_t)(brow + 24) * H_DIM;

    uint32_t smU = smem_u32(sm);
    uint32_t aD = smU + (SM_A + arow * A_STRIDE) * 4 + aq * 16;
    uint32_t bD = smU + (SM_B + brow * B_STRIDE) * 4 + bq * 16;

    int lane = tid & 31, g_ = lane >> 2, tq = lane & 3;
    int wid = tid >> 5;
    int wm = (wid >> 2) * 64, wn = (wid & 3) * 32;

    float c[4][4][4];
    #pragma unroll
    for (int i = 0; i < 4; i++)
        #pragma unroll
        for (int j = 0; j < 4; j++)
            #pragma unroll
            for (int q = 0; q < 4; q++) c[i][j][q] = 0.0f;

#define ISSUE2(CH, BUF) do {                                               \
    size_t k0 = (size_t)(CH) * KC;                                         \
    uint32_t ad = aD + (BUF) * (A_BUF * 4);                                \
    cp16(ad,                       aS0 + k0);                              \
    cp16(ad + 32 * A_STRIDE * 4,   aS1 + k0);                              \
    cp16(ad + 64 * A_STRIDE * 4,   aS2 + k0);                              \
    cp16(ad + 96 * A_STRIDE * 4,   aS3 + k0);                              \
    uint32_t bd = bD + (BUF) * (B_BUF * 4);                                \
    size_t kb = k0 * H_DIM;                                                \
    cp16(bd,                       bS0 + kb);                              \
    cp16(bd + 8  * B_STRIDE * 4,   bS1 + kb);                              \
    cp16(bd + 16 * B_STRIDE * 4,   bS2 + kb);                              \
    cp16(bd + 24 * B_STRIDE * 4,   bS3 + kb); } while (0)

    const int NC = F_DIM / KC;   // 64
    ISSUE2(0, 0);
    CP_COMMIT();

    for (int ch = 0; ch < NC; ch++) {
        int buf = ch & 1;
        if (ch + 1 < NC) { ISSUE2(ch + 1, (ch + 1) & 1); CP_COMMIT(); CP_WAIT(1); }
        else             { CP_WAIT(0); }
        __syncthreads();
        const float* As = sm + SM_A + buf * A_BUF;
        const float* Bs = sm + SM_B + buf * B_BUF;
        #pragma unroll
        for (int kk = 0; kk < 4; kk++) {
            uint32_t af[4][4], bf[4][2];
            #pragma unroll
            for (int mt = 0; mt < 4; mt++) {
                int r = wm + mt * 16 + g_;
                af[mt][0] = __float_as_uint(As[r * A_STRIDE + kk * 8 + tq]);
                af[mt][1] = __float_as_uint(As[(r + 8) * A_STRIDE + kk * 8 + tq]);
                af[mt][2] = __float_as_uint(As[r * A_STRIDE + kk * 8 + tq + 4]);
                af[mt][3] = __float_as_uint(As[(r + 8) * A_STRIDE + kk * 8 + tq + 4]);
            }
            #pragma unroll
            for (int nt = 0; nt < 4; nt++) {
                int cl = wn + nt * 8 + g_;
                bf[nt][0] = __float_as_uint(Bs[(kk * 8 + tq) * B_STRIDE + cl]);
                bf[nt][1] = __float_as_uint(Bs[(kk * 8 + tq + 4) * B_STRIDE + cl]);
            }
            #pragma unroll
            for (int mt = 0; mt < 4; mt++)
                #pragma unroll
                for (int nt = 0; nt < 4; nt++)
                    mma8(c[mt][nt], af[mt], bf[nt]);
        }
        __syncthreads();
    }
#undef ISSUE2

    // epilogue: bias, routing weight, atomic combine
    const float* bp = bias + (size_t)e * H_DIM + n0;
    #pragma unroll
    for (int mt = 0; mt < 4; mt++) {
        #pragma unroll
        for (int half = 0; half < 2; half++) {
            int r = wm + mt * 16 + g_ + half * 8;
            if (r < rowsHere) {
                int slot = sSlot[r];
                float w = tw[slot];
                float* orow = out + (size_t)(slot >> 1) * H_DIM + n0 + wn;
                #pragma unroll
                for (int nt = 0; nt < 4; nt++) {
                    int cb = nt * 8 + 2 * tq;
                    atomicAdd(orow + cb,     w * (c[mt][nt][half * 2 + 0] + bp[wn + cb]));
                    atomicAdd(orow + cb + 1, w * (c[mt][nt][half * 2 + 1] + bp[wn + cb + 1]));
                }
            }
        }
    }
}

extern "C" void kernel_launch(void* const* d_in, const int* in_sizes, int n_in,
                              void* d_out, int out_size) {
    const float* hidden = (const float*)d_in[0];   // [T, H]
    const float* tw     = (const float*)d_in[1];   // [T, K]
    const int*   ids    = (const int*)d_in[2];     // [T, K]
    const float* w1     = (const float*)d_in[3];   // [E, H, 2F]
    const float* b1     = (const float*)d_in[4];   // [E, 2F]
    const float* w2     = (const float*)d_in[5];   // [E, F, H]
    const float* b2     = (const float*)d_in[6];   // [E, H]
    float* out = (float*)d_out;                    // [T, H]

    cudaFuncSetAttribute(k_gemm1, cudaFuncAttributeMaxDynamicSharedMemorySize, SMEM_BYTES);
    cudaFuncSetAttribute(k_gemm2, cudaFuncAttributeMaxDynamicSharedMemorySize, SMEM_BYTES);

    float* d_w1t; cudaGetSymbolAddress((void**)&d_w1t, g_w1);
    float* d_w2t; cudaGetSymbolAddress((void**)&d_w2t, g_w2);
    float* d_hid; cudaGetSymbolAddress((void**)&d_hid, g_hid);

    int n = T_TOK * H_DIM;
    k_init<<<(n + 255) / 256, 256>>>(out);
    k_build<<<(TK + 255) / 256, 256>>>(ids);
    k_tilemap<<<1, 32>>>();
    // pre-round operands to tf32 (RNE)
    k_round<<<(E_NUM * H_DIM * N1 / 4 + 255) / 256, 256>>>(w1, d_w1t, E_NUM * H_DIM * N1 / 4);
    k_round<<<(E_NUM * F_DIM * H_DIM / 4 + 255) / 256, 256>>>(w2, d_w2t, E_NUM * F_DIM * H_DIM / 4);
    k_round<<<(T_TOK * H_DIM / 4 + 255) / 256, 256>>>(hidden, d_hid, T_TOK * H_DIM / 4);

    k_gemm1<<<dim3(N1 / BN, MAX_TILES), 256, SMEM_BYTES>>>(b1);
    k_gemm2<<<dim3(H_DIM / BN, MAX_TILES), 256, SMEM_BYTES>>>(b2, tw, out);
}

// round 13
// speedup vs baseline: 3.6133x; 1.0049x over previous
#include <cuda_runtime.h>
#include <cstdint>

// Problem constants
#define T_TOK 16384
#define H_DIM 1024
#define E_NUM 16
#define F_DIM 2048
#define K_TOP 2
#define TK    (T_TOK * K_TOP)   // 32768
#define N1    (2 * F_DIM)       // 4096
#define BM 128
#define BN 256
#define KC 32
#define MAX_TILES (TK / BM + E_NUM)

// smem layout (float offsets), 3-stage pipeline
#define A_STRIDE 36
#define A_BUF   (BM * A_STRIDE)              // 4608 floats / stage
#define B_STRIDE 264                          // 256 + 8 pad (conflict-free)
#define B_BUF   (KC * B_STRIDE)              // 8448 floats / stage
#define SM_A    128
#define SM_B    (SM_A + 3 * A_BUF)           // 13952
#define SMEM_FLOATS (SM_B + 3 * B_BUF)       // 39296
#define SMEM_BYTES  (SMEM_FLOATS * 4)        // 157184

// -------- device scratch (allocation-free contract) --------
__device__ int   g_counts[E_NUM];
__device__ int   g_slots[E_NUM * TK];
__device__ int   g_numTiles;
__device__ int   g_tileE[MAX_TILES + 8];
__device__ int   g_tileRow[MAX_TILES + 8];
__device__ float g_inter[(size_t)TK * F_DIM];            // 256 MB (tf32-rounded)
__device__ float g_w1[(size_t)E_NUM * H_DIM * N1];       // 256 MB tf32 W1
__device__ float g_w2[(size_t)E_NUM * F_DIM * H_DIM];    // 128 MB tf32 W2
__device__ float g_hid[(size_t)T_TOK * H_DIM];           // 64 MB tf32 hidden

// -------- helpers --------
__device__ __forceinline__ uint32_t smem_u32(const void* p) {
    uint32_t a;
    asm("{ .reg .u64 t; cvta.to.shared.u64 t, %1; cvt.u32.u64 %0, t; }" : "=r"(a) : "l"(p));
    return a;
}
__device__ __forceinline__ uint32_t f2tf(float x) {
    uint32_t r;
    asm("cvt.rna.tf32.f32 %0, %1;" : "=r"(r) : "f"(x));
    return r;
}
__device__ __forceinline__ void cp16(uint32_t dst, const float* src) {
    asm volatile("cp.async.ca.shared.global [%0], [%1], 16;" :: "r"(dst), "l"(src) : "memory");
}
#define CP_COMMIT() asm volatile("cp.async.commit_group;" ::: "memory")
#define CP_WAIT(n)  asm volatile("cp.async.wait_group %0;" :: "n"(n) : "memory")

__device__ __forceinline__ void mma8(float c[4], const uint32_t a[4], const uint32_t b[2]) {
    asm volatile(
        "mma.sync.aligned.m16n8k8.row.col.f32.tf32.tf32.f32 "
        "{%0,%1,%2,%3}, {%4,%5,%6,%7}, {%8,%9}, {%0,%1,%2,%3};"
        : "+f"(c[0]), "+f"(c[1]), "+f"(c[2]), "+f"(c[3])
        : "r"(a[0]), "r"(a[1]), "r"(a[2]), "r"(a[3]), "r"(b[0]), "r"(b[1]));
}

// warp tile 64x64 (mt 0..3 x nt 0..7), one KC=32 chunk (4 k8 steps)
__device__ __forceinline__ void compute_chunk(
    const float* __restrict__ As, const float* __restrict__ Bs,
    float c[4][8][4], int wm, int wn, int g_, int tq)
{
    #pragma unroll
    for (int kk = 0; kk < 4; kk++) {
        uint32_t af[4][4], bf[8][2];
        #pragma unroll
        for (int mt = 0; mt < 4; mt++) {
            int r = wm + mt * 16 + g_;
            af[mt][0] = __float_as_uint(As[r * A_STRIDE + kk * 8 + tq]);
            af[mt][1] = __float_as_uint(As[(r + 8) * A_STRIDE + kk * 8 + tq]);
            af[mt][2] = __float_as_uint(As[r * A_STRIDE + kk * 8 + tq + 4]);
            af[mt][3] = __float_as_uint(As[(r + 8) * A_STRIDE + kk * 8 + tq + 4]);
        }
        #pragma unroll
        for (int nt = 0; nt < 8; nt++) {
            int cl = wn + nt * 8 + g_;
            bf[nt][0] = __float_as_uint(Bs[(kk * 8 + tq) * B_STRIDE + cl]);
            bf[nt][1] = __float_as_uint(Bs[(kk * 8 + tq + 4) * B_STRIDE + cl]);
        }
        #pragma unroll
        for (int mt = 0; mt < 4; mt++)
            #pragma unroll
            for (int nt = 0; nt < 8; nt++)
                mma8(c[mt][nt], af[mt], bf[nt]);
    }
}

// -------- setup kernels --------
__global__ void k_init(float* __restrict__ out) {
    int i = blockIdx.x * blockDim.x + threadIdx.x;
    if (i < T_TOK * H_DIM) out[i] = 0.0f;
    if (i < E_NUM) g_counts[i] = 0;
}
__global__ void k_build(const int* __restrict__ topk_ids) {
    int i = blockIdx.x * blockDim.x + threadIdx.x;
    if (i < TK) {
        int e = topk_ids[i];
        int pos = atomicAdd(&g_counts[e], 1);
        g_slots[e * TK + pos] = i;
    }
}
__global__ void k_tilemap() {
    if (threadIdx.x == 0 && blockIdx.x == 0) {
        int idx = 0;
        for (int e = 0; e < E_NUM; e++) {
            int c = g_counts[e];
            for (int r = 0; r < c; r += BM) { g_tileE[idx] = e; g_tileRow[idx] = r; idx++; }
        }
        g_numTiles = idx;
    }
}
__global__ void k_round(const float* __restrict__ s, float* __restrict__ d, int n4) {
    int i = blockIdx.x * blockDim.x + threadIdx.x;
    if (i < n4) {
        float4 v = ((const float4*)s)[i];
        ((uint4*)d)[i] = make_uint4(f2tf(v.x), f2tf(v.y), f2tf(v.z), f2tf(v.w));
    }
}

// ================= GEMM1: hidden @ W1[e] + b1, swiglu -> g_inter =================
__global__ void __launch_bounds__(256, 1) k_gemm1(const float* __restrict__ bias)
{
    extern __shared__ float sm[];
    int tileIdx = blockIdx.y;
    if (tileIdx >= g_numTiles) return;
    int e = g_tileE[tileIdx], rowStart = g_tileRow[tileIdx];
    int rowsHere = min(BM, g_counts[e] - rowStart);
    int n0 = blockIdx.x * BN;
    int tid = threadIdx.x;

    int* sSlot = (int*)sm;
    if (tid < BM)
        sSlot[tid] = (tid < rowsHere) ? g_slots[e * TK + rowStart + tid]
                                      : g_slots[e * TK + rowStart];
    __syncthreads();

    // A: 4 cp16/thread (rows arow+32i, cols aq*4..aq*4+3)
    int arow = tid >> 3, aq = tid & 7;
    const float* aS0 = g_hid + (size_t)(sSlot[arow]      >> 1) * H_DIM + aq * 4;
    const float* aS1 = g_hid + (size_t)(sSlot[arow + 32] >> 1) * H_DIM + aq * 4;
    const float* aS2 = g_hid + (size_t)(sSlot[arow + 64] >> 1) * H_DIM + aq * 4;
    const float* aS3 = g_hid + (size_t)(sSlot[arow + 96] >> 1) * H_DIM + aq * 4;
    // B: 8 cp16/thread (k-rows brow+4j, cols bq*4)
    int brow = tid >> 6, bq = tid & 63;
    const float* Wb = g_w1 + (size_t)e * H_DIM * N1 + n0 + bq * 4;

    uint32_t smU = smem_u32(sm);
    uint32_t aD = smU + (SM_A + arow * A_STRIDE) * 4 + aq * 16;
    uint32_t bD = smU + (SM_B + brow * B_STRIDE) * 4 + bq * 16;

    int lane = tid & 31, g_ = lane >> 2, tq = lane & 3;
    int wid = tid >> 5;
    int wm = (wid >> 2) * 64, wn = (wid & 3) * 64;

    float c[4][8][4];
    #pragma unroll
    for (int i = 0; i < 4; i++)
        #pragma unroll
        for (int j = 0; j < 8; j++)
            #pragma unroll
            for (int q = 0; q < 4; q++) c[i][j][q] = 0.0f;

#define ISSUE1(CH, ST) do {                                                \
    size_t k0 = (size_t)(CH) * KC;                                         \
    uint32_t ad = aD + (ST) * (A_BUF * 4);                                 \
    cp16(ad,                       aS0 + k0);                              \
    cp16(ad + 32 * A_STRIDE * 4,   aS1 + k0);                              \
    cp16(ad + 64 * A_STRIDE * 4,   aS2 + k0);                              \
    cp16(ad + 96 * A_STRIDE * 4,   aS3 + k0);                              \
    uint32_t bd = bD + (ST) * (B_BUF * 4);                                 \
    const float* wk = Wb + (k0 + brow) * N1;                               \
    _Pragma("unroll")                                                      \
    for (int j = 0; j < 8; j++)                                            \
        cp16(bd + j * 4 * B_STRIDE * 4, wk + (size_t)j * 4 * N1); } while (0)

    const int NC = H_DIM / KC;   // 32
    ISSUE1(0, 0); CP_COMMIT();
    ISSUE1(1, 1); CP_COMMIT();

    for (int ch = 0; ch < NC; ch++) {
        int st = ch % 3;
        if (ch + 2 < NC) { ISSUE1(ch + 2, (ch + 2) % 3); CP_COMMIT(); CP_WAIT(2); }
        else if (ch + 1 < NC) { CP_WAIT(1); }
        else { CP_WAIT(0); }
        __syncthreads();
        compute_chunk(sm + SM_A + st * A_BUF, sm + SM_B + st * B_BUF, c, wm, wn, g_, tq);
        __syncthreads();
    }
#undef ISSUE1

    // epilogue: bias + swiglu, store tf32-rounded to g_inter
    const float* bp = bias + (size_t)e * N1 + n0;
    #pragma unroll
    for (int mt = 0; mt < 4; mt++) {
        #pragma unroll
        for (int half = 0; half < 2; half++) {
            int r = wm + mt * 16 + g_ + half * 8;
            if (r < rowsHere) {
                int slot = sSlot[r];
                float* orow = g_inter + (size_t)slot * F_DIM + (n0 >> 1) + (wn >> 1);
                #pragma unroll
                for (int nt = 0; nt < 8; nt++) {
                    int cb = wn + nt * 8 + 2 * tq;
                    float gt = c[mt][nt][half * 2 + 0] + bp[cb];
                    float up = c[mt][nt][half * 2 + 1] + bp[cb + 1];
                    gt = fminf(gt, 7.0f);
                    up = fminf(fmaxf(up, -7.0f), 7.0f);
                    float glu = gt / (1.0f + __expf(-1.702f * gt));
                    orow[nt * 4 + tq] = __uint_as_float(f2tf((up + 1.0f) * glu));
                }
            }
        }
    }
}

// ================= GEMM2: g_inter @ W2[e] + b2, weighted atomic combine =================
__global__ void __launch_bounds__(256, 1) k_gemm2(
    const float* __restrict__ bias, const float* __restrict__ tw,
    float* __restrict__ out)
{
    extern __shared__ float sm[];
    int tileIdx = blockIdx.y;
    if (tileIdx >= g_numTiles) return;
    int e = g_tileE[tileIdx], rowStart = g_tileRow[tileIdx];
    int rowsHere = min(BM, g_counts[e] - rowStart);
    int n0 = blockIdx.x * BN;
    int tid = threadIdx.x;

    int* sSlot = (int*)sm;
    if (tid < BM)
        sSlot[tid] = (tid < rowsHere) ? g_slots[e * TK + rowStart + tid]
                                      : g_slots[e * TK + rowStart];
    __syncthreads();

    int arow = tid >> 3, aq = tid & 7;
    const float* aS0 = g_inter + (size_t)sSlot[arow]      * F_DIM + aq * 4;
    const float* aS1 = g_inter + (size_t)sSlot[arow + 32] * F_DIM + aq * 4;
    const float* aS2 = g_inter + (size_t)sSlot[arow + 64] * F_DIM + aq * 4;
    const float* aS3 = g_inter + (size_t)sSlot[arow + 96] * F_DIM + aq * 4;
    int brow = tid >> 6, bq = tid & 63;
    const float* Wb = g_w2 + (size_t)e * F_DIM * H_DIM + n0 + bq * 4;

    uint32_t smU = smem_u32(sm);
    uint32_t aD = smU + (SM_A + arow * A_STRIDE) * 4 + aq * 16;
    uint32_t bD = smU + (SM_B + brow * B_STRIDE) * 4 + bq * 16;

    int lane = tid & 31, g_ = lane >> 2, tq = lane & 3;
    int wid = tid >> 5;
    int wm = (wid >> 2) * 64, wn = (wid & 3) * 64;

    float c[4][8][4];
    #pragma unroll
    for (int i = 0; i < 4; i++)
        #pragma unroll
        for (int j = 0; j < 8; j++)
            #pragma unroll
            for (int q = 0; q < 4; q++) c[i][j][q] = 0.0f;

#define ISSUE2(CH, ST) do {                                                \
    size_t k0 = (size_t)(CH) * KC;                                         \
    uint32_t ad = aD + (ST) * (A_BUF * 4);                                 \
    cp16(ad,                       aS0 + k0);                              \
    cp16(ad + 32 * A_STRIDE * 4,   aS1 + k0);                              \
    cp16(ad + 64 * A_STRIDE * 4,   aS2 + k0);                              \
    cp16(ad + 96 * A_STRIDE * 4,   aS3 + k0);                              \
    uint32_t bd = bD + (ST) * (B_BUF * 4);                                 \
    const float* wk = Wb + (k0 + brow) * H_DIM;                            \
    _Pragma("unroll")                                                      \
    for (int j = 0; j < 8; j++)                                            \
        cp16(bd + j * 4 * B_STRIDE * 4, wk + (size_t)j * 4 * H_DIM); } while (0)

    const int NC = F_DIM / KC;   // 64
    ISSUE2(0, 0); CP_COMMIT();
    ISSUE2(1, 1); CP_COMMIT();

    for (int ch = 0; ch < NC; ch++) {
        int st = ch % 3;
        if (ch + 2 < NC) { ISSUE2(ch + 2, (ch + 2) % 3); CP_COMMIT(); CP_WAIT(2); }
        else if (ch + 1 < NC) { CP_WAIT(1); }
        else { CP_WAIT(0); }
        __syncthreads();
        compute_chunk(sm + SM_A + st * A_BUF, sm + SM_B + st * B_BUF, c, wm, wn, g_, tq);
        __syncthreads();
    }
#undef ISSUE2

    // epilogue: bias, routing weight, atomic combine
    const float* bp = bias + (size_t)e * H_DIM + n0;
    #pragma unroll
    for (int mt = 0; mt < 4; mt++) {
        #pragma unroll
        for (int half = 0; half < 2; half++) {
            int r = wm + mt * 16 + g_ + half * 8;
            if (r < rowsHere) {
                int slot = sSlot[r];
                float w = tw[slot];
                float* orow = out + (size_t)(slot >> 1) * H_DIM + n0 + wn;
                #pragma unroll
                for (int nt = 0; nt < 8; nt++) {
                    int cb = nt * 8 + 2 * tq;
                    atomicAdd(orow + cb,     w * (c[mt][nt][half * 2 + 0] + bp[wn + cb]));
                    atomicAdd(orow + cb + 1, w * (c[mt][nt][half * 2 + 1] + bp[wn + cb + 1]));
                }
            }
        }
    }
}

extern "C" void kernel_launch(void* const* d_in, const int* in_sizes, int n_in,
                              void* d_out, int out_size) {
    const float* hidden = (const float*)d_in[0];   // [T, H]
    const float* tw     = (const float*)d_in[1];   // [T, K]
    const int*   ids    = (const int*)d_in[2];     // [T, K]
    const float* w1     = (const float*)d_in[3];   // [E, H, 2F]
    const float* b1     = (const float*)d_in[4];   // [E, 2F]
    const float* w2     = (const float*)d_in[5];   // [E, F, H]
    const float* b2     = (const float*)d_in[6];   // [E, H]
    float* out = (float*)d_out;                    // [T, H]

    cudaFuncSetAttribute(k_gemm1, cudaFuncAttributeMaxDynamicSharedMemorySize, SMEM_BYTES);
    cudaFuncSetAttribute(k_gemm2, cudaFuncAttributeMaxDynamicSharedMemorySize, SMEM_BYTES);

    float* d_w1t; cudaGetSymbolAddress((void**)&d_w1t, g_w1);
    float* d_w2t; cudaGetSymbolAddress((void**)&d_w2t, g_w2);
    float* d_hid; cudaGetSymbolAddress((void**)&d_hid, g_hid);

    int n = T_TOK * H_DIM;
    k_init<<<(n + 255) / 256, 256>>>(out);
    k_build<<<(TK + 255) / 256, 256>>>(ids);
    k_tilemap<<<1, 32>>>();
    // pre-round operands to tf32 (RNE)
    k_round<<<(E_NUM * H_DIM * N1 / 4 + 255) / 256, 256>>>(w1, d_w1t, E_NUM * H_DIM * N1 / 4);
    k_round<<<(E_NUM * F_DIM * H_DIM / 4 + 255) / 256, 256>>>(w2, d_w2t, E_NUM * F_DIM * H_DIM / 4);
    k_round<<<(T_TOK * H_DIM / 4 + 255) / 256, 256>>>(hidden, d_hid, T_TOK * H_DIM / 4);

    k_gemm1<<<dim3(N1 / BN, MAX_TILES), 256, SMEM_BYTES>>>(b1);
    k_gemm2<<<dim3(H_DIM / BN, MAX_TILES), 256, SMEM_BYTES>>>(b2, tw, out);
}

// round 14
// speedup vs baseline: 4.2449x; 1.1748x over previous
#include <cuda_runtime.h>
#include <cuda_fp16.h>
#include <cstdint>

// Problem constants
#define T_TOK 16384
#define H_DIM 1024
#define E_NUM 16
#define F_DIM 2048
#define K_TOP 2
#define TK    (T_TOK * K_TOP)   // 32768
#define N1    (2 * F_DIM)       // 4096
#define BM 128
#define BN 128
#define KC 32
#define MAX_TILES (TK / BM + E_NUM)

// smem (half units), 3-stage pipeline
#define STR   40                       // KC=32 + 8 pad halfs (20-bank stride, conflict-free)
#define ABUF  (BM * STR)               // 5120 halfs / stage
#define BBUF  (BN * STR)               // 5120 halfs / stage
#define AOFF  512                      // bytes (after 128 slot ints)
#define BOFF  (AOFF + 3 * ABUF * 2)    // bytes
#define SMEM_BYTES (BOFF + 3 * BBUF * 2)   // 512 + 61440 = 61952 B

// -------- device scratch (allocation-free contract) --------
__device__ int    g_counts[E_NUM];
__device__ int    g_slots[E_NUM * TK];
__device__ int    g_numTiles;
__device__ int    g_tileE[MAX_TILES + 8];
__device__ int    g_tileRow[MAX_TILES + 8];
__device__ __half g_interh[(size_t)TK * F_DIM];          // 128 MB
__device__ __half g_w1h[(size_t)E_NUM * N1 * H_DIM];     // 128 MB, [E][N1][H] transposed
__device__ __half g_w2h[(size_t)E_NUM * H_DIM * F_DIM];  // 64 MB,  [E][H][F] transposed
__device__ __half g_hidh[(size_t)T_TOK * H_DIM];         // 32 MB

// -------- helpers --------
__device__ __forceinline__ uint32_t smem_u32(const void* p) {
    uint32_t a;
    asm("{ .reg .u64 t; cvta.to.shared.u64 t, %1; cvt.u32.u64 %0, t; }" : "=r"(a) : "l"(p));
    return a;
}
__device__ __forceinline__ void cp16(uint32_t dst, const __half* src) {
    asm volatile("cp.async.ca.shared.global [%0], [%1], 16;" :: "r"(dst), "l"(src) : "memory");
}
#define CP_COMMIT() asm volatile("cp.async.commit_group;" ::: "memory")
#define CP_WAIT(n)  asm volatile("cp.async.wait_group %0;" :: "n"(n) : "memory")

__device__ __forceinline__ void mma16(float c[4], const uint32_t a[4], const uint32_t b[2]) {
    asm volatile(
        "mma.sync.aligned.m16n8k16.row.col.f32.f16.f16.f32 "
        "{%0,%1,%2,%3}, {%4,%5,%6,%7}, {%8,%9}, {%0,%1,%2,%3};"
        : "+f"(c[0]), "+f"(c[1]), "+f"(c[2]), "+f"(c[3])
        : "r"(a[0]), "r"(a[1]), "r"(a[2]), "r"(a[3]), "r"(b[0]), "r"(b[1]));
}

// warp tile 64x32 (mt 0..3 x nt 0..3), one KC=32 chunk = 2 k16 steps
__device__ __forceinline__ void compute_chunk(
    const __half* __restrict__ As, const __half* __restrict__ Bs,
    float c[4][4][4], int wm, int wn, int g_, int tq)
{
    #pragma unroll
    for (int kk = 0; kk < 2; kk++) {
        int kb = kk * 16 + 2 * tq;
        uint32_t af[4][4], bf[4][2];
        #pragma unroll
        for (int mt = 0; mt < 4; mt++) {
            int r = wm + mt * 16 + g_;
            af[mt][0] = *(const uint32_t*)&As[r * STR + kb];
            af[mt][1] = *(const uint32_t*)&As[(r + 8) * STR + kb];
            af[mt][2] = *(const uint32_t*)&As[r * STR + kb + 8];
            af[mt][3] = *(const uint32_t*)&As[(r + 8) * STR + kb + 8];
        }
        #pragma unroll
        for (int nt = 0; nt < 4; nt++) {
            int cl = wn + nt * 8 + g_;
            bf[nt][0] = *(const uint32_t*)&Bs[cl * STR + kb];
            bf[nt][1] = *(const uint32_t*)&Bs[cl * STR + kb + 8];
        }
        #pragma unroll
        for (int mt = 0; mt < 4; mt++)
            #pragma unroll
            for (int nt = 0; nt < 4; nt++)
                mma16(c[mt][nt], af[mt], bf[nt]);
    }
}

// -------- setup kernels --------
__global__ void k_init(float* __restrict__ out) {
    int i = blockIdx.x * blockDim.x + threadIdx.x;
    if (i < T_TOK * H_DIM) out[i] = 0.0f;
    if (i < E_NUM) g_counts[i] = 0;
}
__global__ void k_build(const int* __restrict__ topk_ids) {
    int i = blockIdx.x * blockDim.x + threadIdx.x;
    if (i < TK) {
        int e = topk_ids[i];
        int pos = atomicAdd(&g_counts[e], 1);
        g_slots[e * TK + pos] = i;
    }
}
__global__ void k_tilemap() {
    if (threadIdx.x == 0 && blockIdx.x == 0) {
        int idx = 0;
        for (int e = 0; e < E_NUM; e++) {
            int c = g_counts[e];
            for (int r = 0; r < c; r += BM) { g_tileE[idx] = e; g_tileRow[idx] = r; idx++; }
        }
        g_numTiles = idx;
    }
}
// fp32 -> fp16 elementwise (float4 -> 2x half2 packed into 8B)
__global__ void k_cvt(const float* __restrict__ s, __half* __restrict__ d, int n4) {
    int i = blockIdx.x * blockDim.x + threadIdx.x;
    if (i < n4) {
        float4 v = ((const float4*)s)[i];
        __half2 h0 = __floats2half2_rn(v.x, v.y);
        __half2 h1 = __floats2half2_rn(v.z, v.w);
        uint2 u = make_uint2(*(uint32_t*)&h0, *(uint32_t*)&h1);
        ((uint2*)d)[i] = u;
    }
}
// per-expert transpose + fp16 convert: in [z][R][C] f32 -> out [z][C][R] f16
__global__ void k_transpose(const float* __restrict__ in, __half* __restrict__ out,
                            int R, int C) {
    __shared__ __half tile[32][34];
    const float* ip = in + (size_t)blockIdx.z * R * C;
    __half* op = out + (size_t)blockIdx.z * R * C;
    int x = blockIdx.x * 32 + threadIdx.x;   // C index (coalesced read)
    int y0 = blockIdx.y * 32;                // R base
    #pragma unroll
    for (int j = threadIdx.y; j < 32; j += 8)
        tile[j][threadIdx.x] = __float2half_rn(ip[(size_t)(y0 + j) * C + x]);
    __syncthreads();
    int xo = y0 + threadIdx.x;               // R index (coalesced write)
    int yo0 = blockIdx.x * 32;               // C base -> out row
    #pragma unroll
    for (int j = threadIdx.y; j < 32; j += 8)
        op[(size_t)(yo0 + j) * R + xo] = tile[threadIdx.x][j];
}

// ================= GEMM1: hidden @ W1[e] + b1, swiglu -> g_interh =================
__global__ void __launch_bounds__(256, 2) k_gemm1(const float* __restrict__ bias)
{
    extern __shared__ char smem[];
    int tileIdx = blockIdx.y;
    if (tileIdx >= g_numTiles) return;
    int e = g_tileE[tileIdx], rowStart = g_tileRow[tileIdx];
    int rowsHere = min(BM, g_counts[e] - rowStart);
    int n0 = blockIdx.x * BN;
    int tid = threadIdx.x;

    int* sSlot = (int*)smem;
    if (tid < BM)
        sSlot[tid] = (tid < rowsHere) ? g_slots[e * TK + rowStart + tid]
                                      : g_slots[e * TK + rowStart];
    __syncthreads();

    // loader mapping: row = tid>>1 (2 threads/row), each does 2 cp16 (32B)
    int ldr = tid >> 1, sp8 = (tid & 1) * 16;   // half offset within 32-half row
    const __half* aSrc = g_hidh + (size_t)(sSlot[ldr] >> 1) * H_DIM + sp8;
    const __half* bSrc = g_w1h + (size_t)e * N1 * H_DIM + (size_t)(n0 + ldr) * H_DIM + sp8;
    uint32_t smU = smem_u32(smem);
    uint32_t aD = smU + AOFF + (ldr * STR + sp8) * 2;
    uint32_t bD = smU + BOFF + (ldr * STR + sp8) * 2;

    int lane = tid & 31, g_ = lane >> 2, tq = lane & 3;
    int wid = tid >> 5;
    int wm = (wid >> 2) * 64, wn = (wid & 3) * 32;

    float c[4][4][4];
    #pragma unroll
    for (int i = 0; i < 4; i++)
        #pragma unroll
        for (int j = 0; j < 4; j++)
            #pragma unroll
            for (int q = 0; q < 4; q++) c[i][j][q] = 0.0f;

#define ISSUE1(CH, ST) do {                          \
    int k0 = (CH) * KC;                              \
    uint32_t ad = aD + (ST) * (ABUF * 2);            \
    cp16(ad,      aSrc + k0);                        \
    cp16(ad + 16, aSrc + k0 + 8);                    \
    uint32_t bd = bD + (ST) * (BBUF * 2);            \
    cp16(bd,      bSrc + k0);                        \
    cp16(bd + 16, bSrc + k0 + 8); } while (0)

    const int NC = H_DIM / KC;   // 32
    ISSUE1(0, 0); CP_COMMIT();
    ISSUE1(1, 1); CP_COMMIT();

    const __half* Ah = (const __half*)(smem + AOFF);
    const __half* Bh = (const __half*)(smem + BOFF);
    for (int ch = 0; ch < NC; ch++) {
        int st = ch % 3;
        if (ch + 2 < NC) { ISSUE1(ch + 2, (ch + 2) % 3); CP_COMMIT(); CP_WAIT(2); }
        else if (ch + 1 < NC) { CP_WAIT(1); }
        else { CP_WAIT(0); }
        __syncthreads();
        compute_chunk(Ah + st * ABUF, Bh + st * BBUF, c, wm, wn, g_, tq);
        __syncthreads();
    }
#undef ISSUE1

    // epilogue: bias + swiglu, store fp16 to g_interh
    const float* bp = bias + (size_t)e * N1 + n0;
    #pragma unroll
    for (int mt = 0; mt < 4; mt++) {
        #pragma unroll
        for (int half = 0; half < 2; half++) {
            int r = wm + mt * 16 + g_ + half * 8;
            if (r < rowsHere) {
                int slot = sSlot[r];
                __half* orow = g_interh + (size_t)slot * F_DIM + (n0 >> 1) + (wn >> 1);
                #pragma unroll
                for (int nt = 0; nt < 4; nt++) {
                    int cb = wn + nt * 8 + 2 * tq;
                    float gt = c[mt][nt][half * 2 + 0] + bp[cb];
                    float up = c[mt][nt][half * 2 + 1] + bp[cb + 1];
                    gt = fminf(gt, 7.0f);
                    up = fminf(fmaxf(up, -7.0f), 7.0f);
                    float glu = gt / (1.0f + __expf(-1.702f * gt));
                    orow[nt * 4 + tq] = __float2half_rn((up + 1.0f) * glu);
                }
            }
        }
    }
}

// ================= GEMM2: g_interh @ W2[e] + b2, weighted atomic combine =================
__global__ void __launch_bounds__(256, 2) k_gemm2(
    const float* __restrict__ bias, const float* __restrict__ tw,
    float* __restrict__ out)
{
    extern __shared__ char smem[];
    int tileIdx = blockIdx.y;
    if (tileIdx >= g_numTiles) return;
    int e = g_tileE[tileIdx], rowStart = g_tileRow[tileIdx];
    int rowsHere = min(BM, g_counts[e] - rowStart);
    int n0 = blockIdx.x * BN;
    int tid = threadIdx.x;

    int* sSlot = (int*)smem;
    if (tid < BM)
        sSlot[tid] = (tid < rowsHere) ? g_slots[e * TK + rowStart + tid]
                                      : g_slots[e * TK + rowStart];
    __syncthreads();

    int ldr = tid >> 1, sp8 = (tid & 1) * 16;
    const __half* aSrc = g_interh + (size_t)sSlot[ldr] * F_DIM + sp8;
    const __half* bSrc = g_w2h + (size_t)e * H_DIM * F_DIM + (size_t)(n0 + ldr) * F_DIM + sp8;
    uint32_t smU = smem_u32(smem);
    uint32_t aD = smU + AOFF + (ldr * STR + sp8) * 2;
    uint32_t bD = smU + BOFF + (ldr * STR + sp8) * 2;

    int lane = tid & 31, g_ = lane >> 2, tq = lane & 3;
    int wid = tid >> 5;
    int wm = (wid >> 2) * 64, wn = (wid & 3) * 32;

    float c[4][4][4];
    #pragma unroll
    for (int i = 0; i < 4; i++)
        #pragma unroll
        for (int j = 0; j < 4; j++)
            #pragma unroll
            for (int q = 0; q < 4; q++) c[i][j][q] = 0.0f;

#define ISSUE2(CH, ST) do {                          \
    int k0 = (CH) * KC;                              \
    uint32_t ad = aD + (ST) * (ABUF * 2);            \
    cp16(ad,      aSrc + k0);                        \
    cp16(ad + 16, aSrc + k0 + 8);                    \
    uint32_t bd = bD + (ST) * (BBUF * 2);            \
    cp16(bd,      bSrc + k0);                        \
    cp16(bd + 16, bSrc + k0 + 8); } while (0)

    const int NC = F_DIM / KC;   // 64
    ISSUE2(0, 0); CP_COMMIT();
    ISSUE2(1, 1); CP_COMMIT();

    const __half* Ah = (const __half*)(smem + AOFF);
    const __half* Bh = (const __half*)(smem + BOFF);
    for (int ch = 0; ch < NC; ch++) {
        int st = ch % 3;
        if (ch + 2 < NC) { ISSUE2(ch + 2, (ch + 2) % 3); CP_COMMIT(); CP_WAIT(2); }
        else if (ch + 1 < NC) { CP_WAIT(1); }
        else { CP_WAIT(0); }
        __syncthreads();
        compute_chunk(Ah + st * ABUF, Bh + st * BBUF, c, wm, wn, g_, tq);
        __syncthreads();
    }
#undef ISSUE2

    // epilogue: bias, routing weight, atomic combine
    const float* bp = bias + (size_t)e * H_DIM + n0;
    #pragma unroll
    for (int mt = 0; mt < 4; mt++) {
        #pragma unroll
        for (int half = 0; half < 2; half++) {
            int r = wm + mt * 16 + g_ + half * 8;
            if (r < rowsHere) {
                int slot = sSlot[r];
                float w = tw[slot];
                float* orow = out + (size_t)(slot >> 1) * H_DIM + n0 + wn;
                #pragma unroll
                for (int nt = 0; nt < 4; nt++) {
                    int cb = nt * 8 + 2 * tq;
                    atomicAdd(orow + cb,     w * (c[mt][nt][half * 2 + 0] + bp[wn + cb]));
                    atomicAdd(orow + cb + 1, w * (c[mt][nt][half * 2 + 1] + bp[wn + cb + 1]));
                }
            }
        }
    }
}

extern "C" void kernel_launch(void* const* d_in, const int* in_sizes, int n_in,
                              void* d_out, int out_size) {
    const float* hidden = (const float*)d_in[0];   // [T, H]
    const float* tw     = (const float*)d_in[1];   // [T, K]
    const int*   ids    = (const int*)d_in[2];     // [T, K]
    const float* w1     = (const float*)d_in[3];   // [E, H, 2F]
    const float* b1     = (const float*)d_in[4];   // [E, 2F]
    const float* w2     = (const float*)d_in[5];   // [E, F, H]
    const float* b2     = (const float*)d_in[6];   // [E, H]
    float* out = (float*)d_out;                    // [T, H]

    cudaFuncSetAttribute(k_gemm1, cudaFuncAttributeMaxDynamicSharedMemorySize, SMEM_BYTES);
    cudaFuncSetAttribute(k_gemm2, cudaFuncAttributeMaxDynamicSharedMemorySize, SMEM_BYTES);

    __half* d_w1h;  cudaGetSymbolAddress((void**)&d_w1h, g_w1h);
    __half* d_w2h;  cudaGetSymbolAddress((void**)&d_w2h, g_w2h);
    __half* d_hidh; cudaGetSymbolAddress((void**)&d_hidh, g_hidh);

    int n = T_TOK * H_DIM;
    k_init<<<(n + 255) / 256, 256>>>(out);
    k_build<<<(TK + 255) / 256, 256>>>(ids);
    k_tilemap<<<1, 32>>>();
    // weights: transpose + fp16 ([E][K][N] -> [E][N][K]); hidden: fp16 convert
    k_transpose<<<dim3(N1 / 32, H_DIM / 32, E_NUM), dim3(32, 8)>>>(w1, d_w1h, H_DIM, N1);
    k_transpose<<<dim3(H_DIM / 32, F_DIM / 32, E_NUM), dim3(32, 8)>>>(w2, d_w2h, F_DIM, H_DIM);
    k_cvt<<<(T_TOK * H_DIM / 4 + 255) / 256, 256>>>(hidden, d_hidh, T_TOK * H_DIM / 4);

    k_gemm1<<<dim3(N1 / BN, MAX_TILES), 256, SMEM_BYTES>>>(b1);
    k_gemm2<<<dim3(H_DIM / BN, MAX_TILES), 256, SMEM_BYTES>>>(b2, tw, out);
}

// round 15
// speedup vs baseline: 5.9763x; 1.4079x over previous
#include <cuda_runtime.h>
#include <cuda_fp16.h>
#include <cstdint>

// Problem constants
#define T_TOK 16384
#define H_DIM 1024
#define E_NUM 16
#define F_DIM 2048
#define K_TOP 2
#define TK    (T_TOK * K_TOP)   // 32768
#define N1    (2 * F_DIM)       // 4096
#define BM 128
#define BN 128
#define KC 32
#define MAX_TILES (TK / BM + E_NUM)

// smem (half units), 3-stage pipeline
#define ASTR  40                        // 32 + 8 pad halfs (80B rows, LDSM conflict-free)
#define BSTR  136                       // 128 + 8 pad halfs (272B rows, LDSM conflict-free)
#define ABUF  (BM * ASTR)               // 5120 halfs / stage
#define BBUF  (KC * BSTR)               // 4352 halfs / stage
#define AOFF  512                       // bytes (after 128 slot ints)
#define BOFF  (AOFF + 3 * ABUF * 2)     // 31232
#define SMEM_BYTES (BOFF + 3 * BBUF * 2)  // 57344 B -> 2 CTAs/SM

// -------- device scratch (allocation-free contract) --------
__device__ int    g_counts[E_NUM];
__device__ int    g_slots[E_NUM * TK];
__device__ int    g_numTiles;
__device__ int    g_tileE[MAX_TILES + 8];
__device__ int    g_tileRow[MAX_TILES + 8];
__device__ __half g_interh[(size_t)TK * F_DIM];          // 128 MB
__device__ __half g_w1h[(size_t)E_NUM * H_DIM * N1];     // 128 MB, native [E][H][N1] fp16
__device__ __half g_w2h[(size_t)E_NUM * F_DIM * H_DIM];  // 64 MB,  native [E][F][H] fp16
__device__ __half g_hidh[(size_t)T_TOK * H_DIM];         // 32 MB

// -------- helpers --------
__device__ __forceinline__ uint32_t smem_u32(const void* p) {
    uint32_t a;
    asm("{ .reg .u64 t; cvta.to.shared.u64 t, %1; cvt.u32.u64 %0, t; }" : "=r"(a) : "l"(p));
    return a;
}
__device__ __forceinline__ void cp16(uint32_t dst, const __half* src) {
    asm volatile("cp.async.ca.shared.global [%0], [%1], 16;" :: "r"(dst), "l"(src) : "memory");
}
#define CP_COMMIT() asm volatile("cp.async.commit_group;" ::: "memory")
#define CP_WAIT(n)  asm volatile("cp.async.wait_group %0;" :: "n"(n) : "memory")

__device__ __forceinline__ void ldsm4(uint32_t r[4], uint32_t a) {
    asm volatile("ldmatrix.sync.aligned.m8n8.x4.shared.b16 {%0,%1,%2,%3}, [%4];"
        : "=r"(r[0]), "=r"(r[1]), "=r"(r[2]), "=r"(r[3]) : "r"(a));
}
__device__ __forceinline__ void ldsm4t(uint32_t r[4], uint32_t a) {
    asm volatile("ldmatrix.sync.aligned.m8n8.x4.trans.shared.b16 {%0,%1,%2,%3}, [%4];"
        : "=r"(r[0]), "=r"(r[1]), "=r"(r[2]), "=r"(r[3]) : "r"(a));
}
__device__ __forceinline__ void mma16(float c[4], const uint32_t a[4], const uint32_t b[2]) {
    asm volatile(
        "mma.sync.aligned.m16n8k16.row.col.f32.f16.f16.f32 "
        "{%0,%1,%2,%3}, {%4,%5,%6,%7}, {%8,%9}, {%0,%1,%2,%3};"
        : "+f"(c[0]), "+f"(c[1]), "+f"(c[2]), "+f"(c[3])
        : "r"(a[0]), "r"(a[1]), "r"(a[2]), "r"(a[3]), "r"(b[0]), "r"(b[1]));
}

// warp tile 64x32. aA[4]: per-mt LDSM lane addrs (stage-relative bytes);
// bA[2]: per-n16-pair LDSM.T lane addrs. One KC=32 chunk = 2 k16 steps.
__device__ __forceinline__ void compute_chunk(
    uint32_t aBase, uint32_t bBase, float c[4][4][4],
    const uint32_t aA[4], const uint32_t bA[2])
{
    #pragma unroll
    for (int kk = 0; kk < 2; kk++) {
        uint32_t af[4][4], bf[2][4];
        #pragma unroll
        for (int mt = 0; mt < 4; mt++)
            ldsm4(af[mt], aBase + aA[mt] + kk * 32);              // +16 halfs in K
        #pragma unroll
        for (int p = 0; p < 2; p++)
            ldsm4t(bf[p], bBase + bA[p] + kk * 16 * BSTR * 2);    // +16 K-rows
        #pragma unroll
        for (int mt = 0; mt < 4; mt++)
            #pragma unroll
            for (int p = 0; p < 2; p++) {
                mma16(c[mt][2 * p],     af[mt], &bf[p][0]);       // n = wn+p*16
                mma16(c[mt][2 * p + 1], af[mt], &bf[p][2]);       // n = wn+p*16+8
            }
    }
}

// -------- setup kernels --------
__global__ void k_init(float* __restrict__ out) {
    int i = blockIdx.x * blockDim.x + threadIdx.x;
    if (i < T_TOK * H_DIM) out[i] = 0.0f;
    if (i < E_NUM) g_counts[i] = 0;
}
__global__ void k_build(const int* __restrict__ topk_ids) {
    int i = blockIdx.x * blockDim.x + threadIdx.x;
    if (i < TK) {
        int e = topk_ids[i];
        int pos = atomicAdd(&g_counts[e], 1);
        g_slots[e * TK + pos] = i;
    }
}
__global__ void k_tilemap() {
    if (threadIdx.x == 0 && blockIdx.x == 0) {
        int idx = 0;
        for (int e = 0; e < E_NUM; e++) {
            int c = g_counts[e];
            for (int r = 0; r < c; r += BM) { g_tileE[idx] = e; g_tileRow[idx] = r; idx++; }
        }
        g_numTiles = idx;
    }
}
// fp32 -> fp16 elementwise
__global__ void k_cvt(const float* __restrict__ s, __half* __restrict__ d, int n4) {
    int i = blockIdx.x * blockDim.x + threadIdx.x;
    if (i < n4) {
        float4 v = ((const float4*)s)[i];
        __half2 h0 = __floats2half2_rn(v.x, v.y);
        __half2 h1 = __floats2half2_rn(v.z, v.w);
        uint2 u = make_uint2(*(uint32_t*)&h0, *(uint32_t*)&h1);
        ((uint2*)d)[i] = u;
    }
}

// ================= GEMM1: hidden @ W1[e] + b1, swiglu -> g_interh =================
__global__ void __launch_bounds__(256, 2) k_gemm1(const float* __restrict__ bias)
{
    extern __shared__ char smem[];
    int tileIdx = blockIdx.y;
    if (tileIdx >= g_numTiles) return;
    int e = g_tileE[tileIdx], rowStart = g_tileRow[tileIdx];
    int rowsHere = min(BM, g_counts[e] - rowStart);
    int n0 = blockIdx.x * BN;
    int tid = threadIdx.x;

    int* sSlot = (int*)smem;
    if (tid < BM)
        sSlot[tid] = (tid < rowsHere) ? g_slots[e * TK + rowStart + tid]
                                      : g_slots[e * TK + rowStart];
    __syncthreads();

    // A loader: row = tid>>1, 2x cp16 covering 32 halfs
    int aldr = tid >> 1, asp = (tid & 1) * 16;
    const __half* aSrc = g_hidh + (size_t)(sSlot[aldr] >> 1) * H_DIM + asp;
    // B loader: k-row = tid>>3, 2x cp16 at cols (tid&7)*8 and +64
    int bldr = tid >> 3, bcol = (tid & 7) * 8;
    const __half* bSrc = g_w1h + (size_t)e * H_DIM * N1 + (size_t)bldr * N1 + n0 + bcol;

    uint32_t smU = smem_u32(smem);
    uint32_t aD = smU + AOFF + (aldr * ASTR + asp) * 2;
    uint32_t bD = smU + BOFF + (bldr * BSTR + bcol) * 2;

    int lane = tid & 31, g_ = lane >> 2, tq = lane & 3;
    int wid = tid >> 5;
    int wm = (wid >> 2) * 64, wn = (wid & 3) * 32;

    // LDSM lane addressing: t = lane>>3 (tile), rw = lane&7 (row in tile)
    int lt = lane >> 3, lrw = lane & 7;
    uint32_t aA[4], bA[2];
    #pragma unroll
    for (int mt = 0; mt < 4; mt++)
        aA[mt] = ((wm + mt * 16 + (lt & 1) * 8 + lrw) * ASTR + (lt >> 1) * 8) * 2;
    #pragma unroll
    for (int p = 0; p < 2; p++)
        bA[p] = (((lt & 1) * 8 + lrw) * BSTR + wn + p * 16 + (lt >> 1) * 8) * 2;

    float c[4][4][4];
    #pragma unroll
    for (int i = 0; i < 4; i++)
        #pragma unroll
        for (int j = 0; j < 4; j++)
            #pragma unroll
            for (int q = 0; q < 4; q++) c[i][j][q] = 0.0f;

#define ISSUE1(CH, ST) do {                          \
    int k0 = (CH) * KC;                              \
    uint32_t ad = aD + (ST) * (ABUF * 2);            \
    cp16(ad,      aSrc + k0);                        \
    cp16(ad + 16, aSrc + k0 + 8);                    \
    uint32_t bd = bD + (ST) * (BBUF * 2);            \
    const __half* bs = bSrc + (size_t)k0 * N1;       \
    cp16(bd,       bs);                              \
    cp16(bd + 128, bs + 64); } while (0)

    const int NC = H_DIM / KC;   // 32
    ISSUE1(0, 0); CP_COMMIT();
    ISSUE1(1, 1); CP_COMMIT();

    for (int ch = 0; ch < NC; ch++) {
        int st = ch % 3;
        if (ch + 2 < NC) { ISSUE1(ch + 2, (ch + 2) % 3); CP_COMMIT(); CP_WAIT(2); }
        else if (ch + 1 < NC) { CP_WAIT(1); }
        else { CP_WAIT(0); }
        __syncthreads();
        compute_chunk(smU + AOFF + st * (ABUF * 2), smU + BOFF + st * (BBUF * 2),
                      c, aA, bA);
        __syncthreads();
    }
#undef ISSUE1

    // epilogue: bias + swiglu, store fp16 to g_interh
    const float* bp = bias + (size_t)e * N1 + n0;
    #pragma unroll
    for (int mt = 0; mt < 4; mt++) {
        #pragma unroll
        for (int half = 0; half < 2; half++) {
            int r = wm + mt * 16 + g_ + half * 8;
            if (r < rowsHere) {
                int slot = sSlot[r];
                __half* orow = g_interh + (size_t)slot * F_DIM + (n0 >> 1) + (wn >> 1);
                #pragma unroll
                for (int nt = 0; nt < 4; nt++) {
                    int cb = wn + nt * 8 + 2 * tq;
                    float gt = c[mt][nt][half * 2 + 0] + bp[cb];
                    float up = c[mt][nt][half * 2 + 1] + bp[cb + 1];
                    gt = fminf(gt, 7.0f);
                    up = fminf(fmaxf(up, -7.0f), 7.0f);
                    float glu = gt / (1.0f + __expf(-1.702f * gt));
                    orow[nt * 4 + tq] = __float2half_rn((up + 1.0f) * glu);
                }
            }
        }
    }
}

// ================= GEMM2: g_interh @ W2[e] + b2, weighted atomic combine =================
__global__ void __launch_bounds__(256, 2) k_gemm2(
    const float* __restrict__ bias, const float* __restrict__ tw,
    float* __restrict__ out)
{
    extern __shared__ char smem[];
    int tileIdx = blockIdx.y;
    if (tileIdx >= g_numTiles) return;
    int e = g_tileE[tileIdx], rowStart = g_tileRow[tileIdx];
    int rowsHere = min(BM, g_counts[e] - rowStart);
    int n0 = blockIdx.x * BN;
    int tid = threadIdx.x;

    int* sSlot = (int*)smem;
    if (tid < BM)
        sSlot[tid] = (tid < rowsHere) ? g_slots[e * TK + rowStart + tid]
                                      : g_slots[e * TK + rowStart];
    __syncthreads();

    int aldr = tid >> 1, asp = (tid & 1) * 16;
    const __half* aSrc = g_interh + (size_t)sSlot[aldr] * F_DIM + asp;
    int bldr = tid >> 3, bcol = (tid & 7) * 8;
    const __half* bSrc = g_w2h + (size_t)e * F_DIM * H_DIM + (size_t)bldr * H_DIM + n0 + bcol;

    uint32_t smU = smem_u32(smem);
    uint32_t aD = smU + AOFF + (aldr * ASTR + asp) * 2;
    uint32_t bD = smU + BOFF + (bldr * BSTR + bcol) * 2;

    int lane = tid & 31, g_ = lane >> 2, tq = lane & 3;
    int wid = tid >> 5;
    int wm = (wid >> 2) * 64, wn = (wid & 3) * 32;

    int lt = lane >> 3, lrw = lane & 7;
    uint32_t aA[4], bA[2];
    #pragma unroll
    for (int mt = 0; mt < 4; mt++)
        aA[mt] = ((wm + mt * 16 + (lt & 1) * 8 + lrw) * ASTR + (lt >> 1) * 8) * 2;
    #pragma unroll
    for (int p = 0; p < 2; p++)
        bA[p] = (((lt & 1) * 8 + lrw) * BSTR + wn + p * 16 + (lt >> 1) * 8) * 2;

    float c[4][4][4];
    #pragma unroll
    for (int i = 0; i < 4; i++)
        #pragma unroll
        for (int j = 0; j < 4; j++)
            #pragma unroll
            for (int q = 0; q < 4; q++) c[i][j][q] = 0.0f;

#define ISSUE2(CH, ST) do {                          \
    int k0 = (CH) * KC;                              \
    uint32_t ad = aD + (ST) * (ABUF * 2);            \
    cp16(ad,      aSrc + k0);                        \
    cp16(ad + 16, aSrc + k0 + 8);                    \
    uint32_t bd = bD + (ST) * (BBUF * 2);            \
    const __half* bs = bSrc + (size_t)k0 * H_DIM;    \
    cp16(bd,       bs);                              \
    cp16(bd + 128, bs + 64); } while (0)

    const int NC = F_DIM / KC;   // 64
    ISSUE2(0, 0); CP_COMMIT();
    ISSUE2(1, 1); CP_COMMIT();

    for (int ch = 0; ch < NC; ch++) {
        int st = ch % 3;
        if (ch + 2 < NC) { ISSUE2(ch + 2, (ch + 2) % 3); CP_COMMIT(); CP_WAIT(2); }
        else if (ch + 1 < NC) { CP_WAIT(1); }
        else { CP_WAIT(0); }
        __syncthreads();
        compute_chunk(smU + AOFF + st * (ABUF * 2), smU + BOFF + st * (BBUF * 2),
                      c, aA, bA);
        __syncthreads();
    }
#undef ISSUE2

    // epilogue: bias, routing weight, atomic combine
    const float* bp = bias + (size_t)e * H_DIM + n0;
    #pragma unroll
    for (int mt = 0; mt < 4; mt++) {
        #pragma unroll
        for (int half = 0; half < 2; half++) {
            int r = wm + mt * 16 + g_ + half * 8;
            if (r < rowsHere) {
                int slot = sSlot[r];
                float w = tw[slot];
                float* orow = out + (size_t)(slot >> 1) * H_DIM + n0 + wn;
                #pragma unroll
                for (int nt = 0; nt < 4; nt++) {
                    int cb = nt * 8 + 2 * tq;
                    atomicAdd(orow + cb,     w * (c[mt][nt][half * 2 + 0] + bp[wn + cb]));
                    atomicAdd(orow + cb + 1, w * (c[mt][nt][half * 2 + 1] + bp[wn + cb + 1]));
                }
            }
        }
    }
}

extern "C" void kernel_launch(void* const* d_in, const int* in_sizes, int n_in,
                              void* d_out, int out_size) {
    const float* hidden = (const float*)d_in[0];   // [T, H]
    const float* tw     = (const float*)d_in[1];   // [T, K]
    const int*   ids    = (const int*)d_in[2];     // [T, K]
    const float* w1     = (const float*)d_in[3];   // [E, H, 2F]
    const float* b1     = (const float*)d_in[4];   // [E, 2F]
    const float* w2     = (const float*)d_in[5];   // [E, F, H]
    const float* b2     = (const float*)d_in[6];   // [E, H]
    float* out = (float*)d_out;                    // [T, H]

    cudaFuncSetAttribute(k_gemm1, cudaFuncAttributeMaxDynamicSharedMemorySize, SMEM_BYTES);
    cudaFuncSetAttribute(k_gemm2, cudaFuncAttributeMaxDynamicSharedMemorySize, SMEM_BYTES);

    __half* d_w1h;  cudaGetSymbolAddress((void**)&d_w1h, g_w1h);
    __half* d_w2h;  cudaGetSymbolAddress((void**)&d_w2h, g_w2h);
    __half* d_hidh; cudaGetSymbolAddress((void**)&d_hidh, g_hidh);

    int n = T_TOK * H_DIM;
    k_init<<<(n + 255) / 256, 256>>>(out);
    k_build<<<(TK + 255) / 256, 256>>>(ids);
    k_tilemap<<<1, 32>>>();
    // fp32 -> fp16 converts (no transpose needed; ldmatrix.trans handles B)
    k_cvt<<<(E_NUM * H_DIM * N1 / 4 + 255) / 256, 256>>>(w1, d_w1h, E_NUM * H_DIM * N1 / 4);
    k_cvt<<<(E_NUM * F_DIM * H_DIM / 4 + 255) / 256, 256>>>(w2, d_w2h, E_NUM * F_DIM * H_DIM / 4);
    k_cvt<<<(T_TOK * H_DIM / 4 + 255) / 256, 256>>>(hidden, d_hidh, T_TOK * H_DIM / 4);

    k_gemm1<<<dim3(N1 / BN, MAX_TILES), 256, SMEM_BYTES>>>(b1);
    k_gemm2<<<dim3(H_DIM / BN, MAX_TILES), 256, SMEM_BYTES>>>(b2, tw, out);
}